// round 2
// baseline (speedup 1.0000x reference)
#include <cuda_runtime.h>
#include <cstdint>

#define B_  2
#define N_  2048
#define D_  2048
#define H_  16
#define HD_ 128
#define M_  (B_*N_)              // 4096
#define KVBASE ((size_t)M_*D_)   // floats offset of next_prefix_kv in d_out

// ---------------- scratch (device globals; no allocation) ----------------
__device__ float g_qkv  [(size_t)M_ * 3 * D_];          // [4096, 6144]
__device__ float g_qrope[(size_t)B_ * H_ * N_ * HD_];   // [b,h,n,hd]
__device__ float g_krope[(size_t)B_ * H_ * N_ * HD_];   // [b,h,n,hd]
__device__ float g_attno[(size_t)M_ * D_];              // [b, n, h*hd]

// ---------------- SGEMM: C[M,N] = A[M,K] @ B[K,N] + bias ----------------
// MODE 0: A = param (x),     C = g_qkv
// MODE 1: A = g_attno,       C = param (out)
#define BM 128
#define BN 128
#define BK 16
template <int MODE>
__global__ __launch_bounds__(256, 2)
void sgemm_bias(const float* __restrict__ A_in, const float* __restrict__ Bm,
                const float* __restrict__ bias, float* __restrict__ C_out,
                int M, int N, int K)
{
    const float* A = (MODE == 0) ? A_in : (const float*)g_attno;
    float*       C = (MODE == 0) ? (float*)g_qkv : C_out;

    __shared__ float As[BK][BM];
    __shared__ float Bs[BK][BN];

    const int tid = threadIdx.x;
    const int bx = blockIdx.x;           // N tile
    const int by = blockIdx.y;           // M tile
    const int tx = tid & 15;
    const int ty = tid >> 4;
    const int row0 = ty * 8;
    const int col0 = tx * 8;

    const float* Ab = A + (size_t)by * BM * K;
    const float* Bb = Bm + (size_t)bx * BN;

    float acc[8][8];
#pragma unroll
    for (int i = 0; i < 8; i++)
#pragma unroll
        for (int j = 0; j < 8; j++) acc[i][j] = 0.f;

    for (int k0 = 0; k0 < K; k0 += BK) {
#pragma unroll
        for (int i = 0; i < 2; i++) {
            int idx = tid * 2 + i;               // 0..511
            // A: 128 rows x 4 f4-cols, store transposed
            int ar  = idx >> 2;
            int ac4 = idx & 3;
            float4 av = *(const float4*)(Ab + (size_t)ar * K + k0 + ac4 * 4);
            As[ac4 * 4 + 0][ar] = av.x;
            As[ac4 * 4 + 1][ar] = av.y;
            As[ac4 * 4 + 2][ar] = av.z;
            As[ac4 * 4 + 3][ar] = av.w;
            // B: 16 rows x 32 f4-cols
            int br  = idx >> 5;
            int bc4 = idx & 31;
            *(float4*)(&Bs[br][bc4 * 4]) =
                *(const float4*)(Bb + (size_t)(k0 + br) * N + bc4 * 4);
        }
        __syncthreads();

#pragma unroll
        for (int kk = 0; kk < BK; kk++) {
            float a[8], b[8];
            *(float4*)&a[0] = *(const float4*)&As[kk][row0];
            *(float4*)&a[4] = *(const float4*)&As[kk][row0 + 4];
            *(float4*)&b[0] = *(const float4*)&Bs[kk][col0];
            *(float4*)&b[4] = *(const float4*)&Bs[kk][col0 + 4];
#pragma unroll
            for (int i = 0; i < 8; i++)
#pragma unroll
                for (int j = 0; j < 8; j++) acc[i][j] += a[i] * b[j];
        }
        __syncthreads();
    }

    // epilogue: bias + store
    float bv[8];
#pragma unroll
    for (int j = 0; j < 8; j++) bv[j] = bias[(size_t)bx * BN + col0 + j];
#pragma unroll
    for (int i = 0; i < 8; i++) {
        float* crow = C + (size_t)(by * BM + row0 + i) * N + (size_t)bx * BN + col0;
#pragma unroll
        for (int j = 0; j < 8; j += 4) {
            float4 r;
            r.x = acc[i][j + 0] + bv[j + 0];
            r.y = acc[i][j + 1] + bv[j + 1];
            r.z = acc[i][j + 2] + bv[j + 2];
            r.w = acc[i][j + 3] + bv[j + 3];
            *(float4*)(crow + j) = r;
        }
    }
}

// ---------------- RoPE + scatter (also writes next_prefix_kv) ----------------
__global__ void rope_scatter(const float* __restrict__ fq, const float* __restrict__ fk,
                             float* __restrict__ kvout /* d_out + KVBASE */)
{
    int idx = blockIdx.x * blockDim.x + threadIdx.x;   // B*H*N*64 = 4194304 exactly
    int p = idx & 63;
    int n = (idx >> 6) & (N_ - 1);
    int h = (idx >> 17) & (H_ - 1);
    int b = idx >> 21;

    const float2* row = (const float2*)(g_qkv + (size_t)(b * N_ + n) * 3 * D_);
    int c2 = h * 64 + p;                  // float2 index within one D_ segment
    float2 q = row[c2];
    float2 k = row[c2 + D_ / 2];
    float2 v = row[c2 + D_];

    float aq = fq[n * 64 + p];
    float ak = fk[n * 64 + p];
    float cq, sq, ck, sk;
    sincosf(aq, &sq, &cq);
    sincosf(ak, &sk, &ck);

    size_t bhn = ((size_t)(b * H_ + h) * N_ + n) * 64 + p;   // float2 index [b,h,n,hd]
    ((float2*)g_qrope)[bhn] = make_float2(q.x * cq - q.y * sq, q.x * sq + q.y * cq);
    ((float2*)g_krope)[bhn] = make_float2(k.x * ck - k.y * sk, k.x * sk + k.y * ck);

    // next_prefix_kv: [2, B, H, N, HD] — pre-RoPE k, then v
    float2* kv2 = (float2*)kvout;
    size_t kidx = ((size_t)((0 * B_ + b) * H_ + h) * N_ + n) * 64 + p;
    size_t vidx = ((size_t)((1 * B_ + b) * H_ + h) * N_ + n) * 64 + p;
    kv2[kidx] = k;
    kv2[vidx] = v;
}

// ---------------- Flash attention (fp32, causal) ----------------
#define QT 64
#define KT 32
__global__ __launch_bounds__(256, 2)
void attn_kernel(const float* __restrict__ Vg /* d_out + KVBASE + B*H*N*HD */)
{
    __shared__ float4 Ks4[KT * 32];
    __shared__ float4 Vs4[KT * 32];

    const int tid = threadIdx.x;
    const int h = blockIdx.y, b = blockIdx.z;
    const int q0 = blockIdx.x * QT;
    const int bh = b * H_ + h;
    const int r = tid >> 2;
    const int lane4 = tid & 3;
    const int rg = q0 + r;

    // rotated float4 offsets within a 128-float row (bank-conflict-free)
    int off[8];
#pragma unroll
    for (int mm = 0; mm < 8; mm++) off[mm] = lane4 * 8 + ((mm + 2 * lane4) & 7);

    const float4* qsrc = (const float4*)(g_qrope + ((size_t)bh * N_ + rg) * HD_);
    float4 qf[8];
#pragma unroll
    for (int mm = 0; mm < 8; mm++) qf[mm] = qsrc[off[mm]];

    float4 of[8];
#pragma unroll
    for (int mm = 0; mm < 8; mm++) of[mm] = make_float4(0.f, 0.f, 0.f, 0.f);
    float mx = -1e30f, l = 0.f;

    const float4* Kg4 = (const float4*)(g_krope + (size_t)bh * N_ * HD_);
    const float4* Vg4 = (const float4*)(Vg + (size_t)bh * N_ * HD_);

    const int ntiles = q0 / KT + 2;
    for (int jt = 0; jt < ntiles; jt++) {
        const int j0 = jt * KT;
        __syncthreads();
#pragma unroll
        for (int i = tid; i < KT * 32; i += 256) {
            Ks4[i] = Kg4[(size_t)j0 * 32 + i];
            Vs4[i] = Vg4[(size_t)j0 * 32 + i];
        }
        __syncthreads();
        const bool full = (j0 + KT <= q0);

        for (int j = 0; j < KT; j++) {
            const int jg = j0 + j;
            const float4* kr = &Ks4[j * 32];
            float s = 0.f;
#pragma unroll
            for (int mm = 0; mm < 8; mm++) {
                float4 kk = kr[off[mm]];
                s += qf[mm].x * kk.x + qf[mm].y * kk.y + qf[mm].z * kk.z + qf[mm].w * kk.w;
            }
            s += __shfl_xor_sync(0xffffffffu, s, 1);
            s += __shfl_xor_sync(0xffffffffu, s, 2);

            float sv = s * 0.08838834764831845f;   // 1/sqrt(128)
            if (!full && jg > rg) sv = -1e30f;

            float mn = fmaxf(mx, sv);
            float corr = __expf(mx - mn);
            float pj = __expf(sv - mn);
            l = l * corr + pj;
            mx = mn;

            const float4* vr = &Vs4[j * 32];
#pragma unroll
            for (int mm = 0; mm < 8; mm++) {
                float4 vv = vr[off[mm]];
                of[mm].x = of[mm].x * corr + pj * vv.x;
                of[mm].y = of[mm].y * corr + pj * vv.y;
                of[mm].z = of[mm].z * corr + pj * vv.z;
                of[mm].w = of[mm].w * corr + pj * vv.w;
            }
        }
    }

    const float inv = 1.0f / l;
    float4* dst = (float4*)(g_attno + ((size_t)(b * N_ + rg)) * D_ + h * HD_);
#pragma unroll
    for (int mm = 0; mm < 8; mm++) {
        float4 o = of[mm];
        o.x *= inv; o.y *= inv; o.z *= inv; o.w *= inv;
        dst[off[mm]] = o;
    }
}

// ---------------- launch ----------------
extern "C" void kernel_launch(void* const* d_in, const int* in_sizes, int n_in,
                              void* d_out, int out_size)
{
    const float* x    = (const float*)d_in[0];
    const float* fq   = (const float*)d_in[1];
    const float* fk   = (const float*)d_in[2];
    // d_in[3] = expanded_attn_masks (all ones), d_in[4] = causal mask (tril) — analytic
    const float* Wqkv = (const float*)d_in[5];
    const float* bqkv = (const float*)d_in[6];
    const float* Wout = (const float*)d_in[7];
    const float* bout = (const float*)d_in[8];

    float* out   = (float*)d_out;
    float* kvout = out + KVBASE;
    float* vptr  = kvout + (size_t)B_ * H_ * N_ * HD_;   // v half of next_prefix_kv

    // 1) QKV GEMM: [4096,2048] @ [2048,6144] + bias  (writes g_qkv internally)
    sgemm_bias<0><<<dim3(3 * D_ / BN, M_ / BM), 256>>>(x, Wqkv, bqkv, nullptr, M_, 3 * D_, D_);

    // 2) RoPE q,k + write KV cache (pre-RoPE k, v)
    rope_scatter<<<(B_ * H_ * N_ * 64) / 256, 256>>>(fq, fk, kvout);

    // 3) causal flash attention -> g_attno [b, n, h*hd]
    attn_kernel<<<dim3(N_ / QT, H_, B_), 256>>>(vptr);

    // 4) output GEMM: [4096,2048] @ [2048,2048] + bias -> out  (reads g_attno internally)
    sgemm_bias<1><<<dim3(D_ / BN, M_ / BM), 256>>>(nullptr, Wout, bout, out, M_, D_, D_);
}

// round 5
// speedup vs baseline: 1.4837x; 1.4837x over previous
#include <cuda_runtime.h>
#include <cuda_bf16.h>
#include <cstdint>

#define B_  2
#define N_  2048
#define D_  2048
#define H_  16
#define HD_ 128
#define M_  (B_*N_)              // 4096
#define KVBASE ((size_t)M_*D_)   // floats offset of next_prefix_kv in d_out

// ---------------- scratch (device globals; no allocation) ----------------
__device__ float g_qkv  [(size_t)M_ * 3 * D_];          // [4096, 6144]
__device__ float g_qrope[(size_t)B_ * H_ * N_ * HD_];
__device__ float g_krope[(size_t)B_ * H_ * N_ * HD_];
__device__ float g_attno[(size_t)M_ * D_];              // [b, n, h*hd]
__device__ __nv_bfloat16 g_ahi[(size_t)M_ * D_];        // A hi (x, then attno)
__device__ __nv_bfloat16 g_alo[(size_t)M_ * D_];
__device__ __nv_bfloat16 g_wqkv_hi[(size_t)3 * D_ * D_]; // [6144, 2048] K-major
__device__ __nv_bfloat16 g_wqkv_lo[(size_t)3 * D_ * D_];
__device__ __nv_bfloat16 g_wout_hi[(size_t)D_ * D_];     // [2048, 2048] K-major
__device__ __nv_bfloat16 g_wout_lo[(size_t)D_ * D_];

// ---------------- helpers ----------------
__device__ __forceinline__ uint32_t smem_u32(const void* p) {
    uint32_t a;
    asm("{ .reg .u64 t; cvta.to.shared.u64 t, %1; cvt.u32.u64 %0, t; }" : "=r"(a) : "l"(p));
    return a;
}
__device__ __forceinline__ void cp16(uint32_t dst, const void* src) {
    asm volatile("cp.async.cg.shared.global [%0], [%1], 16;" :: "r"(dst), "l"(src) : "memory");
}
#define CP_COMMIT()  asm volatile("cp.async.commit_group;" ::: "memory")
#define CP_WAIT(n)   asm volatile("cp.async.wait_group %0;" :: "n"(n) : "memory")

__device__ __forceinline__ void ldsm_x4(uint32_t* r, uint32_t a) {
    asm volatile("ldmatrix.sync.aligned.m8n8.x4.shared.b16 {%0,%1,%2,%3}, [%4];"
                 : "=r"(r[0]), "=r"(r[1]), "=r"(r[2]), "=r"(r[3]) : "r"(a));
}
__device__ __forceinline__ void ldsm_x2(uint32_t* r, uint32_t a) {
    asm volatile("ldmatrix.sync.aligned.m8n8.x2.shared.b16 {%0,%1}, [%2];"
                 : "=r"(r[0]), "=r"(r[1]) : "r"(a));
}
__device__ __forceinline__ void mma16816(float* d, const uint32_t* a, const uint32_t* b) {
    asm volatile("mma.sync.aligned.m16n8k16.row.col.f32.bf16.bf16.f32 "
        "{%0,%1,%2,%3}, {%4,%5,%6,%7}, {%8,%9}, {%0,%1,%2,%3};"
        : "+f"(d[0]), "+f"(d[1]), "+f"(d[2]), "+f"(d[3])
        : "r"(a[0]), "r"(a[1]), "r"(a[2]), "r"(a[3]), "r"(b[0]), "r"(b[1]));
}

// ---------------- fp32 -> bf16 hi/lo split (elementwise) ----------------
// SEL 0: src = param (x);  SEL 1: src = g_attno
template <int SEL>
__global__ void conv_split(const float* __restrict__ srcp) {
    const float* src = (SEL == 0) ? srcp : (const float*)g_attno;
    size_t i = (size_t)blockIdx.x * blockDim.x + threadIdx.x;   // per 8 floats
    const float4* s4 = (const float4*)src + i * 2;
    float4 a = s4[0], b = s4[1];
    float v[8] = {a.x, a.y, a.z, a.w, b.x, b.y, b.z, b.w};
    union { __nv_bfloat16 h[8]; uint4 u; } uh, ul;
#pragma unroll
    for (int j = 0; j < 8; j++) {
        uh.h[j] = __float2bfloat16(v[j]);
        ul.h[j] = __float2bfloat16(v[j] - __bfloat162float(uh.h[j]));
    }
    *(uint4*)(g_ahi + i * 8) = uh.u;
    *(uint4*)(g_alo + i * 8) = ul.u;
}

// ---------------- W [K, N] fp32 -> hi/lo [N, K] bf16 (transpose) ----------------
template <int SEL>
__global__ void conv_w(const float* __restrict__ W, int N) {
    __nv_bfloat16* hi = SEL ? g_wout_hi : g_wqkv_hi;
    __nv_bfloat16* lo = SEL ? g_wout_lo : g_wqkv_lo;
    __shared__ float t[32][33];
    int n0 = blockIdx.x * 32, k0 = blockIdx.y * 32;
    int tx = threadIdx.x, ty = threadIdx.y;   // 32 x 8
#pragma unroll
    for (int i = 0; i < 4; i++)
        t[ty + 8 * i][tx] = W[(size_t)(k0 + ty + 8 * i) * N + n0 + tx];
    __syncthreads();
#pragma unroll
    for (int i = 0; i < 4; i++) {
        int n = n0 + ty + 8 * i, k = k0 + tx;
        float v = t[tx][ty + 8 * i];
        __nv_bfloat16 h = __float2bfloat16(v);
        hi[(size_t)n * D_ + k] = h;
        lo[(size_t)n * D_ + k] = __float2bfloat16(v - __bfloat162float(h));
    }
}

// ---------------- mma.sync GEMM: C[M,NN] = A[M,2048] @ W^T + bias ----------------
// 3xBF16 split: Ahi*Bhi + Ahi*Blo + Alo*Bhi, fp32 register accum.
// MODE 0: B = g_wqkv_*, C = g_qkv (NN=6144). MODE 1: B = g_wout_*, C = param (NN=2048).
#define BKG 32
#define TPAD 80                     // bytes per smem row (32 bf16 = 64B + 16B pad)
#define TILE_B (128 * TPAD)         // 10240
#define STG (4 * TILE_B)            // 40960 per stage (Ahi,Alo,Bhi,Blo)
#define GT (D_ / BKG)               // 64 k-iterations

template <int MODE, int NN>
__global__ __launch_bounds__(256, 2)
void gemm_mma(const float* __restrict__ bias, float* __restrict__ Cparam) {
    extern __shared__ __align__(128) char sm[];
    const __nv_bfloat16* Bhi = (MODE == 0) ? g_wqkv_hi : g_wout_hi;
    const __nv_bfloat16* Blo = (MODE == 0) ? g_wqkv_lo : g_wout_lo;
    float* C = (MODE == 0) ? (float*)g_qkv : Cparam;
    const int m0 = blockIdx.y * 128, n0 = blockIdx.x * 128;
    const uint32_t sb = smem_u32(sm);
    const int tid = threadIdx.x, wid = tid >> 5, lane = tid & 31;
    const int wm = (wid >> 2) * 64;     // warp m-offset (0/64)
    const int wn = (wid & 3) * 32;      // warp n-offset (0/32/64/96)

    float d[4][4][4];
#pragma unroll
    for (int i = 0; i < 4; i++)
#pragma unroll
        for (int j = 0; j < 4; j++)
#pragma unroll
            for (int q = 0; q < 4; q++) d[i][j][q] = 0.f;

    // loader: each thread brings 2x16B per tile (r = tid>>1, chunks c,c+1)
    const int lr = tid >> 1, lc = (tid & 1) * 2;
    const uint32_t soff = (uint32_t)(lr * TPAD + lc * 16);
    auto load_tile = [&](int t) {
        const int k0 = t * BKG;
        const uint32_t st = sb + (uint32_t)(t & 1) * STG;
        const size_t ga = (size_t)(m0 + lr) * D_ + k0 + lc * 8;
        const size_t gb = (size_t)(n0 + lr) * D_ + k0 + lc * 8;
        cp16(st + soff,                  g_ahi + ga);
        cp16(st + soff + 16,             g_ahi + ga + 8);
        cp16(st + TILE_B + soff,         g_alo + ga);
        cp16(st + TILE_B + soff + 16,    g_alo + ga + 8);
        cp16(st + 2 * TILE_B + soff,     Bhi + gb);
        cp16(st + 2 * TILE_B + soff + 16, Bhi + gb + 8);
        cp16(st + 3 * TILE_B + soff,     Blo + gb);
        cp16(st + 3 * TILE_B + soff + 16, Blo + gb + 8);
        CP_COMMIT();
    };

    // ldmatrix lane addressing
    const int ar = lane & 15, ac = lane >> 4;          // A: row in 16, k-half
    const int br = lane & 7,  bc = (lane >> 3) & 1;    // B: n in 8, k-half
    const uint32_t aoff = (uint32_t)((wm + ar) * TPAD + ac * 16);
    const uint32_t boff = (uint32_t)((wn + br) * TPAD + bc * 16);

    load_tile(0);

    for (int t = 0; t < GT; t++) {
        if (t + 1 < GT) { load_tile(t + 1); CP_WAIT(1); }
        else            { CP_WAIT(0); }
        __syncthreads();

        const uint32_t st = sb + (uint32_t)(t & 1) * STG;
        uint32_t a[4][4], b[4][2];
#pragma unroll
        for (int ks = 0; ks < 2; ks++) {
            const uint32_t kbo = (uint32_t)(ks * 32);   // 16 bf16 = 32B
            // ---- term Ahi*Bhi ----
#pragma unroll
            for (int mt = 0; mt < 4; mt++)
                ldsm_x4(a[mt], st + aoff + kbo + (uint32_t)(mt * 16 * TPAD));
#pragma unroll
            for (int nt = 0; nt < 4; nt++)
                ldsm_x2(b[nt], st + 2 * TILE_B + boff + kbo + (uint32_t)(nt * 8 * TPAD));
#pragma unroll
            for (int mt = 0; mt < 4; mt++)
#pragma unroll
                for (int nt = 0; nt < 4; nt++) mma16816(d[mt][nt], a[mt], b[nt]);
            // ---- term Ahi*Blo (A cached) ----
#pragma unroll
            for (int nt = 0; nt < 4; nt++)
                ldsm_x2(b[nt], st + 3 * TILE_B + boff + kbo + (uint32_t)(nt * 8 * TPAD));
#pragma unroll
            for (int mt = 0; mt < 4; mt++)
#pragma unroll
                for (int nt = 0; nt < 4; nt++) mma16816(d[mt][nt], a[mt], b[nt]);
            // ---- term Alo*Bhi ----
#pragma unroll
            for (int mt = 0; mt < 4; mt++)
                ldsm_x4(a[mt], st + TILE_B + aoff + kbo + (uint32_t)(mt * 16 * TPAD));
#pragma unroll
            for (int nt = 0; nt < 4; nt++)
                ldsm_x2(b[nt], st + 2 * TILE_B + boff + kbo + (uint32_t)(nt * 8 * TPAD));
#pragma unroll
            for (int mt = 0; mt < 4; mt++)
#pragma unroll
                for (int nt = 0; nt < 4; nt++) mma16816(d[mt][nt], a[mt], b[nt]);
        }
        __syncthreads();
    }

    // epilogue: d regs -> C with bias. row = lane>>2 (+8), col = 2*(lane&3) (+1)
    const int erow = lane >> 2, ecol = (lane & 3) * 2;
#pragma unroll
    for (int mt = 0; mt < 4; mt++) {
#pragma unroll
        for (int nt = 0; nt < 4; nt++) {
            const int col = n0 + wn + nt * 8 + ecol;
            const float2 bv = *(const float2*)(bias + col);
            const int row = m0 + wm + mt * 16 + erow;
            float2 v0 = make_float2(d[mt][nt][0] + bv.x, d[mt][nt][1] + bv.y);
            float2 v1 = make_float2(d[mt][nt][2] + bv.x, d[mt][nt][3] + bv.y);
            *(float2*)(C + (size_t)row * NN + col)       = v0;
            *(float2*)(C + (size_t)(row + 8) * NN + col) = v1;
        }
    }
}

// ---------------- RoPE + scatter (also writes next_prefix_kv) ----------------
__global__ void rope_scatter(const float* __restrict__ fq, const float* __restrict__ fk,
                             float* __restrict__ kvout) {
    int idx = blockIdx.x * blockDim.x + threadIdx.x;
    int p = idx & 63;
    int n = (idx >> 6) & (N_ - 1);
    int h = (idx >> 17) & (H_ - 1);
    int b = idx >> 21;

    const float2* row = (const float2*)(g_qkv + (size_t)(b * N_ + n) * 3 * D_);
    int c2 = h * 64 + p;
    float2 q = row[c2];
    float2 k = row[c2 + D_ / 2];
    float2 v = row[c2 + D_];

    float aq = fq[n * 64 + p];
    float ak = fk[n * 64 + p];
    float cq, sq, ck, sk;
    sincosf(aq, &sq, &cq);
    sincosf(ak, &sk, &ck);

    size_t bhn = ((size_t)(b * H_ + h) * N_ + n) * 64 + p;
    ((float2*)g_qrope)[bhn] = make_float2(q.x * cq - q.y * sq, q.x * sq + q.y * cq);
    ((float2*)g_krope)[bhn] = make_float2(k.x * ck - k.y * sk, k.x * sk + k.y * ck);

    float2* kv2 = (float2*)kvout;
    size_t kidx = ((size_t)((0 * B_ + b) * H_ + h) * N_ + n) * 64 + p;
    size_t vidx = ((size_t)((1 * B_ + b) * H_ + h) * N_ + n) * 64 + p;
    kv2[kidx] = k;
    kv2[vidx] = v;
}

// ---------------- Flash attention (fp32, causal) ----------------
#define QT 64
#define KT 32
__global__ __launch_bounds__(256, 2)
void attn_kernel(const float* __restrict__ Vg) {
    __shared__ float4 Ks4[KT * 32];
    __shared__ float4 Vs4[KT * 32];

    const int tid = threadIdx.x;
    const int h = blockIdx.y, b = blockIdx.z;
    const int q0 = blockIdx.x * QT;
    const int bh = b * H_ + h;
    const int r = tid >> 2;
    const int lane4 = tid & 3;
    const int rg = q0 + r;

    int off[8];
#pragma unroll
    for (int mm = 0; mm < 8; mm++) off[mm] = lane4 * 8 + ((mm + 2 * lane4) & 7);

    const float4* qsrc = (const float4*)(g_qrope + ((size_t)bh * N_ + rg) * HD_);
    float4 qf[8];
#pragma unroll
    for (int mm = 0; mm < 8; mm++) qf[mm] = qsrc[off[mm]];

    float4 of[8];
#pragma unroll
    for (int mm = 0; mm < 8; mm++) of[mm] = make_float4(0.f, 0.f, 0.f, 0.f);
    float mx = -1e30f, l = 0.f;

    const float4* Kg4 = (const float4*)(g_krope + (size_t)bh * N_ * HD_);
    const float4* Vg4 = (const float4*)(Vg + (size_t)bh * N_ * HD_);

    const int ntiles = q0 / KT + 2;
    for (int jt = 0; jt < ntiles; jt++) {
        const int j0 = jt * KT;
        __syncthreads();
#pragma unroll
        for (int i = tid; i < KT * 32; i += 256) {
            Ks4[i] = Kg4[(size_t)j0 * 32 + i];
            Vs4[i] = Vg4[(size_t)j0 * 32 + i];
        }
        __syncthreads();
        const bool full = (j0 + KT <= q0);

        for (int j = 0; j < KT; j++) {
            const int jg = j0 + j;
            const float4* kr = &Ks4[j * 32];
            float s = 0.f;
#pragma unroll
            for (int mm = 0; mm < 8; mm++) {
                float4 kk = kr[off[mm]];
                s += qf[mm].x * kk.x + qf[mm].y * kk.y + qf[mm].z * kk.z + qf[mm].w * kk.w;
            }
            s += __shfl_xor_sync(0xffffffffu, s, 1);
            s += __shfl_xor_sync(0xffffffffu, s, 2);

            float sv = s * 0.08838834764831845f;
            if (!full && jg > rg) sv = -1e30f;

            float mn = fmaxf(mx, sv);
            float corr = __expf(mx - mn);
            float pj = __expf(sv - mn);
            l = l * corr + pj;
            mx = mn;

            const float4* vr = &Vs4[j * 32];
#pragma unroll
            for (int mm = 0; mm < 8; mm++) {
                float4 vv = vr[off[mm]];
                of[mm].x = of[mm].x * corr + pj * vv.x;
                of[mm].y = of[mm].y * corr + pj * vv.y;
                of[mm].z = of[mm].z * corr + pj * vv.z;
                of[mm].w = of[mm].w * corr + pj * vv.w;
            }
        }
    }

    const float inv = 1.0f / l;
    float4* dst = (float4*)(g_attno + ((size_t)(b * N_ + rg)) * D_ + h * HD_);
#pragma unroll
    for (int mm = 0; mm < 8; mm++) {
        float4 o = of[mm];
        o.x *= inv; o.y *= inv; o.z *= inv; o.w *= inv;
        dst[off[mm]] = o;
    }
}

// ---------------- launch ----------------
extern "C" void kernel_launch(void* const* d_in, const int* in_sizes, int n_in,
                              void* d_out, int out_size) {
    const float* x    = (const float*)d_in[0];
    const float* fq   = (const float*)d_in[1];
    const float* fk   = (const float*)d_in[2];
    const float* Wqkv = (const float*)d_in[5];
    const float* bqkv = (const float*)d_in[6];
    const float* Wout = (const float*)d_in[7];
    const float* bout = (const float*)d_in[8];

    float* out   = (float*)d_out;
    float* kvout = out + KVBASE;
    float* vptr  = kvout + (size_t)B_ * H_ * N_ * HD_;

    const int smem_gemm = 2 * STG;   // 81,920 B
    cudaFuncSetAttribute(gemm_mma<0, 3 * D_>, cudaFuncAttributeMaxDynamicSharedMemorySize, smem_gemm);
    cudaFuncSetAttribute(gemm_mma<1, D_>,     cudaFuncAttributeMaxDynamicSharedMemorySize, smem_gemm);

    // 0) convert inputs to bf16 hi/lo
    conv_split<0><<<(M_ * D_ / 8) / 256, 256>>>(x);
    conv_w<0><<<dim3(3 * D_ / 32, D_ / 32), dim3(32, 8)>>>(Wqkv, 3 * D_);
    conv_w<1><<<dim3(D_ / 32, D_ / 32), dim3(32, 8)>>>(Wout, D_);

    // 1) QKV GEMM (mma.sync bf16 3-split) -> g_qkv
    gemm_mma<0, 3 * D_><<<dim3(3 * D_ / 128, M_ / 128), 256, smem_gemm>>>(bqkv, nullptr);

    // 2) RoPE q,k + write KV cache
    rope_scatter<<<(B_ * H_ * N_ * 64) / 256, 256>>>(fq, fk, kvout);

    // 3) causal flash attention -> g_attno
    attn_kernel<<<dim3(N_ / QT, H_, B_), 256>>>(vptr);

    // 4) convert attention output, then out GEMM -> d_out
    conv_split<1><<<(M_ * D_ / 8) / 256, 256>>>(x);
    gemm_mma<1, D_><<<dim3(D_ / 128, M_ / 128), 256, smem_gemm>>>(bout, out);
}

// round 6
// speedup vs baseline: 3.3089x; 2.2302x over previous
#include <cuda_runtime.h>
#include <cuda_bf16.h>
#include <cstdint>

#define B_  2
#define N_  2048
#define D_  2048
#define H_  16
#define HD_ 128
#define M_  (B_*N_)              // 4096
#define KVBASE ((size_t)M_*D_)   // floats offset of next_prefix_kv in d_out

// ---------------- scratch (device globals; no allocation) ----------------
__device__ float g_qkv  [(size_t)M_ * 3 * D_];          // [4096, 6144]
__device__ float g_attno[(size_t)M_ * D_];              // [b, n, h*hd]
__device__ __nv_bfloat16 g_ahi[(size_t)M_ * D_];        // A hi (x, then attno)
__device__ __nv_bfloat16 g_alo[(size_t)M_ * D_];
__device__ __nv_bfloat16 g_wqkv_hi[(size_t)3 * D_ * D_]; // [6144, 2048] K-major
__device__ __nv_bfloat16 g_wqkv_lo[(size_t)3 * D_ * D_];
__device__ __nv_bfloat16 g_wout_hi[(size_t)D_ * D_];     // [2048, 2048] K-major
__device__ __nv_bfloat16 g_wout_lo[(size_t)D_ * D_];
// per-head bf16 operands for attention [b,h,n,128]
__device__ __nv_bfloat16 g_qh[(size_t)B_ * H_ * N_ * HD_];
__device__ __nv_bfloat16 g_ql[(size_t)B_ * H_ * N_ * HD_];
__device__ __nv_bfloat16 g_kh[(size_t)B_ * H_ * N_ * HD_];
__device__ __nv_bfloat16 g_kl[(size_t)B_ * H_ * N_ * HD_];
__device__ __nv_bfloat16 g_vh[(size_t)B_ * H_ * N_ * HD_];
__device__ __nv_bfloat16 g_vl[(size_t)B_ * H_ * N_ * HD_];

// ---------------- helpers ----------------
__device__ __forceinline__ uint32_t smem_u32(const void* p) {
    uint32_t a;
    asm("{ .reg .u64 t; cvta.to.shared.u64 t, %1; cvt.u32.u64 %0, t; }" : "=r"(a) : "l"(p));
    return a;
}
__device__ __forceinline__ void cp16(uint32_t dst, const void* src) {
    asm volatile("cp.async.cg.shared.global [%0], [%1], 16;" :: "r"(dst), "l"(src) : "memory");
}
#define CP_COMMIT()  asm volatile("cp.async.commit_group;" ::: "memory")
#define CP_WAIT(n)   asm volatile("cp.async.wait_group %0;" :: "n"(n) : "memory")

__device__ __forceinline__ void ldsm_x4(uint32_t* r, uint32_t a) {
    asm volatile("ldmatrix.sync.aligned.m8n8.x4.shared.b16 {%0,%1,%2,%3}, [%4];"
                 : "=r"(r[0]), "=r"(r[1]), "=r"(r[2]), "=r"(r[3]) : "r"(a));
}
__device__ __forceinline__ void ldsm_x4t(uint32_t* r, uint32_t a) {
    asm volatile("ldmatrix.sync.aligned.m8n8.x4.trans.shared.b16 {%0,%1,%2,%3}, [%4];"
                 : "=r"(r[0]), "=r"(r[1]), "=r"(r[2]), "=r"(r[3]) : "r"(a));
}
__device__ __forceinline__ void ldsm_x2(uint32_t* r, uint32_t a) {
    asm volatile("ldmatrix.sync.aligned.m8n8.x2.shared.b16 {%0,%1}, [%2];"
                 : "=r"(r[0]), "=r"(r[1]) : "r"(a));
}
__device__ __forceinline__ void mma16816(float* d, const uint32_t* a, const uint32_t* b) {
    asm volatile("mma.sync.aligned.m16n8k16.row.col.f32.bf16.bf16.f32 "
        "{%0,%1,%2,%3}, {%4,%5,%6,%7}, {%8,%9}, {%0,%1,%2,%3};"
        : "+f"(d[0]), "+f"(d[1]), "+f"(d[2]), "+f"(d[3])
        : "r"(a[0]), "r"(a[1]), "r"(a[2]), "r"(a[3]), "r"(b[0]), "r"(b[1]));
}
__device__ __forceinline__ float ex2f(float x) {
    float r; asm("ex2.approx.f32 %0, %1;" : "=f"(r) : "f"(x)); return r;
}
// pack two fp32 into bf16x2 with hi/lo residual split; low half = v0
__device__ __forceinline__ void split2(float v0, float v1, uint32_t& hi, uint32_t& lo) {
    uint32_t h;
    asm("cvt.rn.bf16x2.f32 %0, %1, %2;" : "=r"(h) : "f"(v1), "f"(v0));
    __nv_bfloat162 hb = *(__nv_bfloat162*)&h;
    float r0 = v0 - __bfloat162float(hb.x);
    float r1 = v1 - __bfloat162float(hb.y);
    uint32_t lw;
    asm("cvt.rn.bf16x2.f32 %0, %1, %2;" : "=r"(lw) : "f"(r1), "f"(r0));
    hi = h; lo = lw;
}

// ---------------- fp32 -> bf16 hi/lo split (elementwise) ----------------
template <int SEL>
__global__ void conv_split(const float* __restrict__ srcp) {
    const float* src = (SEL == 0) ? srcp : (const float*)g_attno;
    size_t i = (size_t)blockIdx.x * blockDim.x + threadIdx.x;   // per 8 floats
    const float4* s4 = (const float4*)src + i * 2;
    float4 a = s4[0], b = s4[1];
    float v[8] = {a.x, a.y, a.z, a.w, b.x, b.y, b.z, b.w};
    union { __nv_bfloat16 h[8]; uint4 u; } uh, ul;
#pragma unroll
    for (int j = 0; j < 8; j++) {
        uh.h[j] = __float2bfloat16(v[j]);
        ul.h[j] = __float2bfloat16(v[j] - __bfloat162float(uh.h[j]));
    }
    *(uint4*)(g_ahi + i * 8) = uh.u;
    *(uint4*)(g_alo + i * 8) = ul.u;
}

// ---------------- W [K, N] fp32 -> hi/lo [N, K] bf16 (transpose) ----------------
template <int SEL>
__global__ void conv_w(const float* __restrict__ W, int N) {
    __nv_bfloat16* hi = SEL ? g_wout_hi : g_wqkv_hi;
    __nv_bfloat16* lo = SEL ? g_wout_lo : g_wqkv_lo;
    __shared__ float t[32][33];
    int n0 = blockIdx.x * 32, k0 = blockIdx.y * 32;
    int tx = threadIdx.x, ty = threadIdx.y;   // 32 x 8
#pragma unroll
    for (int i = 0; i < 4; i++)
        t[ty + 8 * i][tx] = W[(size_t)(k0 + ty + 8 * i) * N + n0 + tx];
    __syncthreads();
#pragma unroll
    for (int i = 0; i < 4; i++) {
        int n = n0 + ty + 8 * i, k = k0 + tx;
        float v = t[tx][ty + 8 * i];
        __nv_bfloat16 h = __float2bfloat16(v);
        hi[(size_t)n * D_ + k] = h;
        lo[(size_t)n * D_ + k] = __float2bfloat16(v - __bfloat162float(h));
    }
}

// ---------------- mma.sync GEMM (unchanged from R5) ----------------
#define BKG 32
#define TPAD 80
#define TILE_B (128 * TPAD)
#define STG (4 * TILE_B)
#define GT (D_ / BKG)

template <int MODE, int NN>
__global__ __launch_bounds__(256, 2)
void gemm_mma(const float* __restrict__ bias, float* __restrict__ Cparam) {
    extern __shared__ __align__(128) char sm[];
    const __nv_bfloat16* Bhi = (MODE == 0) ? g_wqkv_hi : g_wout_hi;
    const __nv_bfloat16* Blo = (MODE == 0) ? g_wqkv_lo : g_wout_lo;
    float* C = (MODE == 0) ? (float*)g_qkv : Cparam;
    const int m0 = blockIdx.y * 128, n0 = blockIdx.x * 128;
    const uint32_t sb = smem_u32(sm);
    const int tid = threadIdx.x, wid = tid >> 5, lane = tid & 31;
    const int wm = (wid >> 2) * 64;
    const int wn = (wid & 3) * 32;

    float d[4][4][4];
#pragma unroll
    for (int i = 0; i < 4; i++)
#pragma unroll
        for (int j = 0; j < 4; j++)
#pragma unroll
            for (int q = 0; q < 4; q++) d[i][j][q] = 0.f;

    const int lr = tid >> 1, lc = (tid & 1) * 2;
    const uint32_t soff = (uint32_t)(lr * TPAD + lc * 16);
    auto load_tile = [&](int t) {
        const int k0 = t * BKG;
        const uint32_t st = sb + (uint32_t)(t & 1) * STG;
        const size_t ga = (size_t)(m0 + lr) * D_ + k0 + lc * 8;
        const size_t gb = (size_t)(n0 + lr) * D_ + k0 + lc * 8;
        cp16(st + soff,                   g_ahi + ga);
        cp16(st + soff + 16,              g_ahi + ga + 8);
        cp16(st + TILE_B + soff,          g_alo + ga);
        cp16(st + TILE_B + soff + 16,     g_alo + ga + 8);
        cp16(st + 2 * TILE_B + soff,      Bhi + gb);
        cp16(st + 2 * TILE_B + soff + 16, Bhi + gb + 8);
        cp16(st + 3 * TILE_B + soff,      Blo + gb);
        cp16(st + 3 * TILE_B + soff + 16, Blo + gb + 8);
        CP_COMMIT();
    };

    const int ar = lane & 15, ac = lane >> 4;
    const int br = lane & 7,  bc = (lane >> 3) & 1;
    const uint32_t aoff = (uint32_t)((wm + ar) * TPAD + ac * 16);
    const uint32_t boff = (uint32_t)((wn + br) * TPAD + bc * 16);

    load_tile(0);

    for (int t = 0; t < GT; t++) {
        if (t + 1 < GT) { load_tile(t + 1); CP_WAIT(1); }
        else            { CP_WAIT(0); }
        __syncthreads();

        const uint32_t st = sb + (uint32_t)(t & 1) * STG;
        uint32_t a[4][4], b[4][2];
#pragma unroll
        for (int ks = 0; ks < 2; ks++) {
            const uint32_t kbo = (uint32_t)(ks * 32);
#pragma unroll
            for (int mt = 0; mt < 4; mt++)
                ldsm_x4(a[mt], st + aoff + kbo + (uint32_t)(mt * 16 * TPAD));
#pragma unroll
            for (int nt = 0; nt < 4; nt++)
                ldsm_x2(b[nt], st + 2 * TILE_B + boff + kbo + (uint32_t)(nt * 8 * TPAD));
#pragma unroll
            for (int mt = 0; mt < 4; mt++)
#pragma unroll
                for (int nt = 0; nt < 4; nt++) mma16816(d[mt][nt], a[mt], b[nt]);
#pragma unroll
            for (int nt = 0; nt < 4; nt++)
                ldsm_x2(b[nt], st + 3 * TILE_B + boff + kbo + (uint32_t)(nt * 8 * TPAD));
#pragma unroll
            for (int mt = 0; mt < 4; mt++)
#pragma unroll
                for (int nt = 0; nt < 4; nt++) mma16816(d[mt][nt], a[mt], b[nt]);
#pragma unroll
            for (int mt = 0; mt < 4; mt++)
                ldsm_x4(a[mt], st + TILE_B + aoff + kbo + (uint32_t)(mt * 16 * TPAD));
#pragma unroll
            for (int nt = 0; nt < 4; nt++)
                ldsm_x2(b[nt], st + 2 * TILE_B + boff + kbo + (uint32_t)(nt * 8 * TPAD));
#pragma unroll
            for (int mt = 0; mt < 4; mt++)
#pragma unroll
                for (int nt = 0; nt < 4; nt++) mma16816(d[mt][nt], a[mt], b[nt]);
        }
        __syncthreads();
    }

    const int erow = lane >> 2, ecol = (lane & 3) * 2;
#pragma unroll
    for (int mt = 0; mt < 4; mt++) {
#pragma unroll
        for (int nt = 0; nt < 4; nt++) {
            const int col = n0 + wn + nt * 8 + ecol;
            const float2 bv = *(const float2*)(bias + col);
            const int row = m0 + wm + mt * 16 + erow;
            float2 v0 = make_float2(d[mt][nt][0] + bv.x, d[mt][nt][1] + bv.y);
            float2 v1 = make_float2(d[mt][nt][2] + bv.x, d[mt][nt][3] + bv.y);
            *(float2*)(C + (size_t)row * NN + col)       = v0;
            *(float2*)(C + (size_t)(row + 8) * NN + col) = v1;
        }
    }
}

// ---------------- RoPE + bf16 hi/lo emit + KV cache ----------------
__global__ void rope_scatter(const float* __restrict__ fq, const float* __restrict__ fk,
                             float* __restrict__ kvout) {
    int idx = blockIdx.x * blockDim.x + threadIdx.x;   // B*H*N*64
    int p = idx & 63;
    int n = (idx >> 6) & (N_ - 1);
    int h = (idx >> 17) & (H_ - 1);
    int b = idx >> 21;

    const float2* row = (const float2*)(g_qkv + (size_t)(b * N_ + n) * 3 * D_);
    int c2 = h * 64 + p;
    float2 q = row[c2];
    float2 k = row[c2 + D_ / 2];
    float2 v = row[c2 + D_];

    float aq = fq[n * 64 + p];
    float ak = fk[n * 64 + p];
    float cq, sq, ck, sk;
    sincosf(aq, &sq, &cq);
    sincosf(ak, &sk, &ck);

    const float SCL = 0.08838834764831845f * 1.4426950408889634f;  // log2e/sqrt(128)
    float q0 = (q.x * cq - q.y * sq) * SCL;
    float q1 = (q.x * sq + q.y * cq) * SCL;
    float k0 = k.x * ck - k.y * sk;
    float k1 = k.x * sk + k.y * ck;

    uint32_t qh, ql, kh, kl, vh, vl;
    split2(q0, q1, qh, ql);
    split2(k0, k1, kh, kl);
    split2(v.x, v.y, vh, vl);

    size_t bhn = ((size_t)(b * H_ + h) * N_ + n) * 64 + p;   // bf16x2 index
    ((uint32_t*)g_qh)[bhn] = qh;  ((uint32_t*)g_ql)[bhn] = ql;
    ((uint32_t*)g_kh)[bhn] = kh;  ((uint32_t*)g_kl)[bhn] = kl;
    ((uint32_t*)g_vh)[bhn] = vh;  ((uint32_t*)g_vl)[bhn] = vl;

    // next_prefix_kv: [2, B, H, N, HD] — pre-RoPE k, then v (fp32)
    float2* kv2 = (float2*)kvout;
    size_t kidx = ((size_t)((0 * B_ + b) * H_ + h) * N_ + n) * 64 + p;
    size_t vidx = ((size_t)((1 * B_ + b) * H_ + h) * N_ + n) * 64 + p;
    kv2[kidx] = k;
    kv2[vidx] = v;
}

// ---------------- mma.sync flash attention (bf16 3-split, causal) ----------------
// CTA: 128 q-rows x 64-key tiles. 8 warps, each 16 rows x 128 dims.
// smem: Q area (hi+lo, 128x272B each) + 2 stages x (Khi,Klo,Vhi,Vlo 64x272B each)
#define APITCH 272
#define QAREA  (2 * 128 * APITCH)    // 69632
#define KVBUF  (64 * APITCH)         // 17408
#define ASTAGE (4 * KVBUF)           // 69632
#define ASMEM  (QAREA + 2 * ASTAGE)  // 208896

__global__ __launch_bounds__(256, 1)
void attn_mma() {
    extern __shared__ __align__(128) char sm[];
    const int tid = threadIdx.x, wid = tid >> 5, lane = tid & 31;
    const int h = blockIdx.y, b = blockIdx.z;
    const int q0 = (gridDim.x - 1 - blockIdx.x) * 128;   // big tiles first
    const int bh = b * H_ + h;
    const size_t hb = (size_t)bh * N_ * HD_;

    const uint32_t sb = smem_u32(sm);
    const uint32_t qhs = sb, qls = sb + (uint32_t)(128 * APITCH);

    // ---- stage Q (hi+lo) ----
    {
        const int rowq = tid >> 1, chq = (tid & 1) * 8;  // 256 thr x 8 iters = 2048/buf
#pragma unroll
        for (int c = 0; c < 8; c++) {
            int row = rowq, ch = chq + c;                 // ch 0..15
            uint32_t d = (uint32_t)(row * APITCH + ch * 16);
            size_t g = hb + (size_t)(q0 + row) * HD_ + ch * 8;
            cp16(qhs + d, g_qh + g);
            cp16(qls + d, g_ql + g);
        }
        CP_COMMIT();
    }

    auto load_kv = [&](int t) {
        const int j0 = t * 64;
        const uint32_t stg = sb + QAREA + (uint32_t)(t & 1) * ASTAGE;
#pragma unroll
        for (int c = 0; c < 16; c++) {
            int idx = tid + 256 * c;          // 0..4095
            int buf = idx >> 10, rem = idx & 1023;
            int row = rem >> 4, ch = rem & 15;
            const __nv_bfloat16* src = (buf == 0) ? g_kh : (buf == 1) ? g_kl
                                     : (buf == 2) ? g_vh : g_vl;
            cp16(stg + (uint32_t)(buf * KVBUF + row * APITCH + ch * 16),
                 src + hb + (size_t)(j0 + row) * HD_ + ch * 8);
        }
        CP_COMMIT();
    };

    load_kv(0);

    float o[16][4];
#pragma unroll
    for (int i = 0; i < 16; i++)
#pragma unroll
        for (int j = 0; j < 4; j++) o[i][j] = 0.f;
    float m0r = -1e30f, m1r = -1e30f, l0 = 0.f, l1 = 0.f;

    const int rg0 = q0 + 16 * wid + (lane >> 2);
    const int rg1 = rg0 + 8;
    const uint32_t qoff = (uint32_t)((16 * wid + (lane & 15)) * APITCH + ((lane >> 4) & 1) * 16);
    // K (non-trans) per-lane base: key = 16*ntp + 8*((lane>>4)&1) + (lane&7); dim half sel (lane>>3)&1
    const uint32_t kbase = (uint32_t)((lane & 7) * APITCH + ((lane >> 4) & 1) * 8 * APITCH
                                      + ((lane >> 3) & 1) * 16);
    // V (trans) per-lane base: key = 16*kf + (lane&7) + 8*((lane>>3)&1); dim half sel (lane>>4)&1
    const uint32_t vbase = (uint32_t)((lane & 7) * APITCH + ((lane >> 3) & 1) * 8 * APITCH
                                      + ((lane >> 4) & 1) * 16);

    const int ntiles = q0 / 64 + 2;
    for (int t = 0; t < ntiles; t++) {
        if (t + 1 < ntiles) { load_kv(t + 1); CP_WAIT(1); }
        else                { CP_WAIT(0); }
        __syncthreads();

        const uint32_t stg = sb + QAREA + (uint32_t)(t & 1) * ASTAGE;
        const uint32_t khi_s = stg, klo_s = stg + KVBUF;
        const uint32_t vhi_s = stg + 2 * KVBUF, vlo_s = stg + 3 * KVBUF;
        const int j0 = t * 64;

        // ---- scores S[16, 64] per warp (3-term) ----
        float sf[8][4];
#pragma unroll
        for (int i = 0; i < 8; i++)
#pragma unroll
            for (int j = 0; j < 4; j++) sf[i][j] = 0.f;

#pragma unroll
        for (int kf = 0; kf < 8; kf++) {
            uint32_t ah[4], al[4];
            ldsm_x4(ah, qhs + qoff + (uint32_t)(kf * 32));
            ldsm_x4(al, qls + qoff + (uint32_t)(kf * 32));
            uint32_t kb[8][2], kl2[8][2];
#pragma unroll
            for (int ntp = 0; ntp < 4; ntp++) {
                uint32_t r4[4];
                ldsm_x4(r4, khi_s + kbase + (uint32_t)(ntp * 16 * APITCH + kf * 32));
                kb[2 * ntp][0] = r4[0]; kb[2 * ntp][1] = r4[1];
                kb[2 * ntp + 1][0] = r4[2]; kb[2 * ntp + 1][1] = r4[3];
                ldsm_x4(r4, klo_s + kbase + (uint32_t)(ntp * 16 * APITCH + kf * 32));
                kl2[2 * ntp][0] = r4[0]; kl2[2 * ntp][1] = r4[1];
                kl2[2 * ntp + 1][0] = r4[2]; kl2[2 * ntp + 1][1] = r4[3];
            }
#pragma unroll
            for (int nt = 0; nt < 8; nt++) {
                mma16816(sf[nt], ah, kb[nt]);
                mma16816(sf[nt], ah, kl2[nt]);
                mma16816(sf[nt], al, kb[nt]);
            }
        }

        // ---- causal mask (last two tiles only) ----
        if (t >= ntiles - 2) {
            const int cb = j0 + 2 * (lane & 3);
#pragma unroll
            for (int nt = 0; nt < 8; nt++) {
                int jg = cb + 8 * nt;
                if (jg > rg0)     sf[nt][0] = -1e30f;
                if (jg + 1 > rg0) sf[nt][1] = -1e30f;
                if (jg > rg1)     sf[nt][2] = -1e30f;
                if (jg + 1 > rg1) sf[nt][3] = -1e30f;
            }
        }

        // ---- online softmax (scores already in log2 domain) ----
        float mt0 = -1e30f, mt1 = -1e30f;
#pragma unroll
        for (int nt = 0; nt < 8; nt++) {
            mt0 = fmaxf(mt0, fmaxf(sf[nt][0], sf[nt][1]));
            mt1 = fmaxf(mt1, fmaxf(sf[nt][2], sf[nt][3]));
        }
        mt0 = fmaxf(mt0, __shfl_xor_sync(0xffffffffu, mt0, 1));
        mt0 = fmaxf(mt0, __shfl_xor_sync(0xffffffffu, mt0, 2));
        mt1 = fmaxf(mt1, __shfl_xor_sync(0xffffffffu, mt1, 1));
        mt1 = fmaxf(mt1, __shfl_xor_sync(0xffffffffu, mt1, 2));
        float mn0 = fmaxf(m0r, mt0), mn1 = fmaxf(m1r, mt1);
        float c0 = ex2f(m0r - mn0), c1 = ex2f(m1r - mn1);
        m0r = mn0; m1r = mn1;
        float s0 = 0.f, s1 = 0.f;
#pragma unroll
        for (int nt = 0; nt < 8; nt++) {
            sf[nt][0] = ex2f(sf[nt][0] - mn0);
            sf[nt][1] = ex2f(sf[nt][1] - mn0);
            sf[nt][2] = ex2f(sf[nt][2] - mn1);
            sf[nt][3] = ex2f(sf[nt][3] - mn1);
            s0 += sf[nt][0] + sf[nt][1];
            s1 += sf[nt][2] + sf[nt][3];
        }
        s0 += __shfl_xor_sync(0xffffffffu, s0, 1);
        s0 += __shfl_xor_sync(0xffffffffu, s0, 2);
        s1 += __shfl_xor_sync(0xffffffffu, s1, 1);
        s1 += __shfl_xor_sync(0xffffffffu, s1, 2);
        l0 = l0 * c0 + s0;
        l1 = l1 * c1 + s1;
#pragma unroll
        for (int nt = 0; nt < 16; nt++) {
            o[nt][0] *= c0; o[nt][1] *= c0; o[nt][2] *= c1; o[nt][3] *= c1;
        }

        // ---- P·V (3-term) ----
#pragma unroll
        for (int kf = 0; kf < 4; kf++) {
            uint32_t ph[4], pl[4];
            split2(sf[2 * kf][0],     sf[2 * kf][1],     ph[0], pl[0]);
            split2(sf[2 * kf][2],     sf[2 * kf][3],     ph[1], pl[1]);
            split2(sf[2 * kf + 1][0], sf[2 * kf + 1][1], ph[2], pl[2]);
            split2(sf[2 * kf + 1][2], sf[2 * kf + 1][3], ph[3], pl[3]);
#pragma unroll
            for (int ntp = 0; ntp < 8; ntp++) {
                uint32_t vh4[4], vl4[4];
                const uint32_t va = vbase + (uint32_t)(kf * 16 * APITCH + ntp * 32);
                ldsm_x4t(vh4, vhi_s + va);
                ldsm_x4t(vl4, vlo_s + va);
                mma16816(o[2 * ntp],     ph, vh4);
                mma16816(o[2 * ntp],     ph, vl4);
                mma16816(o[2 * ntp],     pl, vh4);
                mma16816(o[2 * ntp + 1], ph, vh4 + 2);
                mma16816(o[2 * ntp + 1], ph, vl4 + 2);
                mma16816(o[2 * ntp + 1], pl, vh4 + 2);
            }
        }
        __syncthreads();
    }

    // ---- epilogue: normalize + store to g_attno [b, n, h*128+dim] ----
    const float inv0 = 1.f / l0, inv1 = 1.f / l1;
    const int cb = h * HD_ + 2 * (lane & 3);
#pragma unroll
    for (int nt = 0; nt < 16; nt++) {
        const int col = cb + 8 * nt;
        *(float2*)(g_attno + (size_t)(b * N_ + rg0) * D_ + col) =
            make_float2(o[nt][0] * inv0, o[nt][1] * inv0);
        *(float2*)(g_attno + (size_t)(b * N_ + rg1) * D_ + col) =
            make_float2(o[nt][2] * inv1, o[nt][3] * inv1);
    }
}

// ---------------- launch ----------------
extern "C" void kernel_launch(void* const* d_in, const int* in_sizes, int n_in,
                              void* d_out, int out_size) {
    const float* x    = (const float*)d_in[0];
    const float* fq   = (const float*)d_in[1];
    const float* fk   = (const float*)d_in[2];
    const float* Wqkv = (const float*)d_in[5];
    const float* bqkv = (const float*)d_in[6];
    const float* Wout = (const float*)d_in[7];
    const float* bout = (const float*)d_in[8];

    float* out   = (float*)d_out;
    float* kvout = out + KVBASE;

    const int smem_gemm = 2 * STG;   // 81,920 B
    cudaFuncSetAttribute(gemm_mma<0, 3 * D_>, cudaFuncAttributeMaxDynamicSharedMemorySize, smem_gemm);
    cudaFuncSetAttribute(gemm_mma<1, D_>,     cudaFuncAttributeMaxDynamicSharedMemorySize, smem_gemm);
    cudaFuncSetAttribute(attn_mma, cudaFuncAttributeMaxDynamicSharedMemorySize, ASMEM);

    // 0) convert inputs to bf16 hi/lo
    conv_split<0><<<(M_ * D_ / 8) / 256, 256>>>(x);
    conv_w<0><<<dim3(3 * D_ / 32, D_ / 32), dim3(32, 8)>>>(Wqkv, 3 * D_);
    conv_w<1><<<dim3(D_ / 32, D_ / 32), dim3(32, 8)>>>(Wout, D_);

    // 1) QKV GEMM -> g_qkv
    gemm_mma<0, 3 * D_><<<dim3(3 * D_ / 128, M_ / 128), 256, smem_gemm>>>(bqkv, nullptr);

    // 2) RoPE + bf16 hi/lo operands + fp32 KV cache
    rope_scatter<<<(B_ * H_ * N_ * 64) / 256, 256>>>(fq, fk, kvout);

    // 3) mma flash attention -> g_attno
    attn_mma<<<dim3(N_ / 128, H_, B_), 256, ASMEM>>>();

    // 4) convert attention output, then out GEMM -> d_out
    conv_split<1><<<(M_ * D_ / 8) / 256, 256>>>(x);
    gemm_mma<1, D_><<<dim3(D_ / 128, M_ / 128), 256, smem_gemm>>>(bout, out);
}

// round 7
// speedup vs baseline: 4.5319x; 1.3696x over previous
#include <cuda_runtime.h>
#include <cuda_bf16.h>
#include <cuda_fp16.h>
#include <cstdint>

#define B_  2
#define N_  2048
#define D_  2048
#define H_  16
#define HD_ 128
#define M_  (B_*N_)              // 4096
#define KVBASE ((size_t)M_*D_)   // floats offset of next_prefix_kv in d_out

// ---------------- scratch (device globals; no allocation) ----------------
__device__ float g_qkv[(size_t)M_ * 3 * D_];            // [4096, 6144]
__device__ __half g_ah[(size_t)M_ * D_];                // A operand fp16 (x, then attn out)
__device__ __half g_wqkv_h[(size_t)3 * D_ * D_];        // [6144, 2048] K-major
__device__ __half g_wqkv_l[(size_t)3 * D_ * D_];
__device__ __half g_wout_h[(size_t)D_ * D_];            // [2048, 2048] K-major
__device__ __half g_wout_l[(size_t)D_ * D_];
// per-head bf16 operands for attention [b,h,n,128]
__device__ __nv_bfloat16 g_qh[(size_t)B_ * H_ * N_ * HD_];
__device__ __nv_bfloat16 g_ql[(size_t)B_ * H_ * N_ * HD_];
__device__ __nv_bfloat16 g_kh[(size_t)B_ * H_ * N_ * HD_];
__device__ __nv_bfloat16 g_kl[(size_t)B_ * H_ * N_ * HD_];
__device__ __nv_bfloat16 g_vh[(size_t)B_ * H_ * N_ * HD_];
__device__ __nv_bfloat16 g_vl[(size_t)B_ * H_ * N_ * HD_];

// ---------------- helpers ----------------
__device__ __forceinline__ uint32_t smem_u32(const void* p) {
    uint32_t a;
    asm("{ .reg .u64 t; cvta.to.shared.u64 t, %1; cvt.u32.u64 %0, t; }" : "=r"(a) : "l"(p));
    return a;
}
__device__ __forceinline__ void cp16(uint32_t dst, const void* src) {
    asm volatile("cp.async.cg.shared.global [%0], [%1], 16;" :: "r"(dst), "l"(src) : "memory");
}
#define CP_COMMIT()  asm volatile("cp.async.commit_group;" ::: "memory")
#define CP_WAIT(n)   asm volatile("cp.async.wait_group %0;" :: "n"(n) : "memory")

__device__ __forceinline__ void ldsm_x4(uint32_t* r, uint32_t a) {
    asm volatile("ldmatrix.sync.aligned.m8n8.x4.shared.b16 {%0,%1,%2,%3}, [%4];"
                 : "=r"(r[0]), "=r"(r[1]), "=r"(r[2]), "=r"(r[3]) : "r"(a));
}
__device__ __forceinline__ void ldsm_x4t(uint32_t* r, uint32_t a) {
    asm volatile("ldmatrix.sync.aligned.m8n8.x4.trans.shared.b16 {%0,%1,%2,%3}, [%4];"
                 : "=r"(r[0]), "=r"(r[1]), "=r"(r[2]), "=r"(r[3]) : "r"(a));
}
__device__ __forceinline__ void ldsm_x2(uint32_t* r, uint32_t a) {
    asm volatile("ldmatrix.sync.aligned.m8n8.x2.shared.b16 {%0,%1}, [%2];"
                 : "=r"(r[0]), "=r"(r[1]) : "r"(a));
}
__device__ __forceinline__ void mma_bf(float* d, const uint32_t* a, const uint32_t* b) {
    asm volatile("mma.sync.aligned.m16n8k16.row.col.f32.bf16.bf16.f32 "
        "{%0,%1,%2,%3}, {%4,%5,%6,%7}, {%8,%9}, {%0,%1,%2,%3};"
        : "+f"(d[0]), "+f"(d[1]), "+f"(d[2]), "+f"(d[3])
        : "r"(a[0]), "r"(a[1]), "r"(a[2]), "r"(a[3]), "r"(b[0]), "r"(b[1]));
}
__device__ __forceinline__ void mma_fp(float* d, const uint32_t* a, const uint32_t* b) {
    asm volatile("mma.sync.aligned.m16n8k16.row.col.f32.f16.f16.f32 "
        "{%0,%1,%2,%3}, {%4,%5,%6,%7}, {%8,%9}, {%0,%1,%2,%3};"
        : "+f"(d[0]), "+f"(d[1]), "+f"(d[2]), "+f"(d[3])
        : "r"(a[0]), "r"(a[1]), "r"(a[2]), "r"(a[3]), "r"(b[0]), "r"(b[1]));
}
__device__ __forceinline__ float ex2f(float x) {
    float r; asm("ex2.approx.f32 %0, %1;" : "=f"(r) : "f"(x)); return r;
}
// pack two fp32 into bf16x2 with hi/lo residual split; low half = v0
__device__ __forceinline__ void split2(float v0, float v1, uint32_t& hi, uint32_t& lo) {
    uint32_t h;
    asm("cvt.rn.bf16x2.f32 %0, %1, %2;" : "=r"(h) : "f"(v1), "f"(v0));
    __nv_bfloat162 hb = *(__nv_bfloat162*)&h;
    float r0 = v0 - __bfloat162float(hb.x);
    float r1 = v1 - __bfloat162float(hb.y);
    uint32_t lw;
    asm("cvt.rn.bf16x2.f32 %0, %1, %2;" : "=r"(lw) : "f"(r1), "f"(r0));
    hi = h; lo = lw;
}

// ---------------- x fp32 -> fp16 (A operand for QKV GEMM) ----------------
__global__ void conv_a(const float* __restrict__ src) {
    size_t i = (size_t)blockIdx.x * blockDim.x + threadIdx.x;   // per 8 floats
    const float4* s4 = (const float4*)src + i * 2;
    float4 a = s4[0], b = s4[1];
    float v[8] = {a.x, a.y, a.z, a.w, b.x, b.y, b.z, b.w};
    union { __half h[8]; uint4 u; } uh;
#pragma unroll
    for (int j = 0; j < 8; j++) uh.h[j] = __float2half_rn(v[j]);
    *(uint4*)(g_ah + i * 8) = uh.u;
}

// ---------------- W [K, N] fp32 -> fp16 hi/lo [N, K] (transpose) ----------------
template <int SEL>
__global__ void conv_w(const float* __restrict__ W, int N) {
    __half* hi = SEL ? g_wout_h : g_wqkv_h;
    __half* lo = SEL ? g_wout_l : g_wqkv_l;
    __shared__ float t[32][33];
    int n0 = blockIdx.x * 32, k0 = blockIdx.y * 32;
    int tx = threadIdx.x, ty = threadIdx.y;   // 32 x 8
#pragma unroll
    for (int i = 0; i < 4; i++)
        t[ty + 8 * i][tx] = W[(size_t)(k0 + ty + 8 * i) * N + n0 + tx];
    __syncthreads();
#pragma unroll
    for (int i = 0; i < 4; i++) {
        int n = n0 + ty + 8 * i, k = k0 + tx;
        float v = t[tx][ty + 8 * i];
        __half h = __float2half_rn(v);
        hi[(size_t)n * D_ + k] = h;
        lo[(size_t)n * D_ + k] = __float2half_rn(v - __half2float(h));
    }
}

// ---------------- fp16 mma GEMM: C[M,NN] = A[M,2048] @ W^T + bias ----------------
// A single fp16, W = Whi + Wlo (2-term): C = A*Whi + A*Wlo, fp32 accum.
#define BKG 32
#define TPAD 80
#define TILE_B (128 * TPAD)     // 10240 per buffer
#define STG (3 * TILE_B)        // A, Wh, Wl -> 30720 per stage
#define GT (D_ / BKG)           // 64

template <int MODE, int NN>
__global__ __launch_bounds__(256, 2)
void gemm_mma(const float* __restrict__ bias, float* __restrict__ Cparam) {
    extern __shared__ __align__(128) char sm[];
    const __half* Wh = (MODE == 0) ? g_wqkv_h : g_wout_h;
    const __half* Wl = (MODE == 0) ? g_wqkv_l : g_wout_l;
    float* C = (MODE == 0) ? (float*)g_qkv : Cparam;
    const int m0 = blockIdx.y * 128, n0 = blockIdx.x * 128;
    const uint32_t sb = smem_u32(sm);
    const int tid = threadIdx.x, wid = tid >> 5, lane = tid & 31;
    const int wm = (wid >> 2) * 64;
    const int wn = (wid & 3) * 32;

    float d[4][4][4];
#pragma unroll
    for (int i = 0; i < 4; i++)
#pragma unroll
        for (int j = 0; j < 4; j++)
#pragma unroll
            for (int q = 0; q < 4; q++) d[i][j][q] = 0.f;

    // loader: 3 buffers x 512 chunks = 1536 chunks, 6 per thread
    auto load_tile = [&](int t) {
        const int k0 = t * BKG;
        const uint32_t st = sb + (uint32_t)(t & 1) * STG;
#pragma unroll
        for (int c = 0; c < 6; c++) {
            int idx = tid + 256 * c;           // 0..1535
            int buf = idx >> 9, rem = idx & 511;
            int row = rem >> 2, ch = rem & 3;
            const __half* sp = (buf == 0) ? (g_ah + (size_t)(m0 + row) * D_)
                             : (buf == 1) ? (Wh + (size_t)(n0 + row) * D_)
                                          : (Wl + (size_t)(n0 + row) * D_);
            cp16(st + (uint32_t)(buf * TILE_B + row * TPAD + ch * 16),
                 sp + k0 + ch * 8);
        }
        CP_COMMIT();
    };

    const int ar = lane & 15, ac = lane >> 4;
    const int br = lane & 7,  bc = (lane >> 3) & 1;
    const uint32_t aoff = (uint32_t)((wm + ar) * TPAD + ac * 16);
    const uint32_t boff = (uint32_t)((wn + br) * TPAD + bc * 16);

    load_tile(0);

    for (int t = 0; t < GT; t++) {
        if (t + 1 < GT) { load_tile(t + 1); CP_WAIT(1); }
        else            { CP_WAIT(0); }
        __syncthreads();

        const uint32_t st = sb + (uint32_t)(t & 1) * STG;
        uint32_t a[4][4], bh[4][2], bl[4][2];
#pragma unroll
        for (int ks = 0; ks < 2; ks++) {
            const uint32_t kbo = (uint32_t)(ks * 32);
#pragma unroll
            for (int mt = 0; mt < 4; mt++)
                ldsm_x4(a[mt], st + aoff + kbo + (uint32_t)(mt * 16 * TPAD));
#pragma unroll
            for (int nt = 0; nt < 4; nt++) {
                ldsm_x2(bh[nt], st + TILE_B + boff + kbo + (uint32_t)(nt * 8 * TPAD));
                ldsm_x2(bl[nt], st + 2 * TILE_B + boff + kbo + (uint32_t)(nt * 8 * TPAD));
            }
#pragma unroll
            for (int mt = 0; mt < 4; mt++)
#pragma unroll
                for (int nt = 0; nt < 4; nt++) mma_fp(d[mt][nt], a[mt], bh[nt]);
#pragma unroll
            for (int mt = 0; mt < 4; mt++)
#pragma unroll
                for (int nt = 0; nt < 4; nt++) mma_fp(d[mt][nt], a[mt], bl[nt]);
        }
        __syncthreads();
    }

    const int erow = lane >> 2, ecol = (lane & 3) * 2;
#pragma unroll
    for (int mt = 0; mt < 4; mt++) {
#pragma unroll
        for (int nt = 0; nt < 4; nt++) {
            const int col = n0 + wn + nt * 8 + ecol;
            const float2 bv = *(const float2*)(bias + col);
            const int row = m0 + wm + mt * 16 + erow;
            float2 v0 = make_float2(d[mt][nt][0] + bv.x, d[mt][nt][1] + bv.y);
            float2 v1 = make_float2(d[mt][nt][2] + bv.x, d[mt][nt][3] + bv.y);
            *(float2*)(C + (size_t)row * NN + col)       = v0;
            *(float2*)(C + (size_t)(row + 8) * NN + col) = v1;
        }
    }
}

// ---------------- RoPE + bf16 hi/lo emit + KV cache ----------------
__global__ void rope_scatter(const float* __restrict__ fq, const float* __restrict__ fk,
                             float* __restrict__ kvout) {
    int idx = blockIdx.x * blockDim.x + threadIdx.x;   // B*H*N*64
    int p = idx & 63;
    int n = (idx >> 6) & (N_ - 1);
    int h = (idx >> 17) & (H_ - 1);
    int b = idx >> 21;

    const float2* row = (const float2*)(g_qkv + (size_t)(b * N_ + n) * 3 * D_);
    int c2 = h * 64 + p;
    float2 q = row[c2];
    float2 k = row[c2 + D_ / 2];
    float2 v = row[c2 + D_];

    float aq = fq[n * 64 + p];
    float ak = fk[n * 64 + p];
    float cq, sq, ck, sk;
    sincosf(aq, &sq, &cq);
    sincosf(ak, &sk, &ck);

    const float SCL = 0.08838834764831845f * 1.4426950408889634f;  // log2e/sqrt(128)
    float q0 = (q.x * cq - q.y * sq) * SCL;
    float q1 = (q.x * sq + q.y * cq) * SCL;
    float k0 = k.x * ck - k.y * sk;
    float k1 = k.x * sk + k.y * ck;

    uint32_t qh, ql, kh, kl, vh, vl;
    split2(q0, q1, qh, ql);
    split2(k0, k1, kh, kl);
    split2(v.x, v.y, vh, vl);

    size_t bhn = ((size_t)(b * H_ + h) * N_ + n) * 64 + p;   // bf16x2 index
    ((uint32_t*)g_qh)[bhn] = qh;  ((uint32_t*)g_ql)[bhn] = ql;
    ((uint32_t*)g_kh)[bhn] = kh;  ((uint32_t*)g_kl)[bhn] = kl;
    ((uint32_t*)g_vh)[bhn] = vh;  ((uint32_t*)g_vl)[bhn] = vl;

    // next_prefix_kv: [2, B, H, N, HD] — pre-RoPE k, then v (fp32)
    float2* kv2 = (float2*)kvout;
    size_t kidx = ((size_t)((0 * B_ + b) * H_ + h) * N_ + n) * 64 + p;
    size_t vidx = ((size_t)((1 * B_ + b) * H_ + h) * N_ + n) * 64 + p;
    kv2[kidx] = k;
    kv2[vidx] = v;
}

// ---------------- mma flash attention (bf16 3-split, causal) ----------------
#define APITCH 272
#define QAREA  (2 * 128 * APITCH)
#define KVBUF  (64 * APITCH)
#define ASTAGE (4 * KVBUF)
#define ASMEM  (QAREA + 2 * ASTAGE)   // 208896

__global__ __launch_bounds__(256, 1)
void attn_mma() {
    extern __shared__ __align__(128) char sm[];
    const int tid = threadIdx.x, wid = tid >> 5, lane = tid & 31;
    const int h = blockIdx.y, b = blockIdx.z;
    const int q0 = (gridDim.x - 1 - blockIdx.x) * 128;
    const int bh = b * H_ + h;
    const size_t hb = (size_t)bh * N_ * HD_;

    const uint32_t sb = smem_u32(sm);
    const uint32_t qhs = sb, qls = sb + (uint32_t)(128 * APITCH);

    {
        const int rowq = tid >> 1, chq = (tid & 1) * 8;
#pragma unroll
        for (int c = 0; c < 8; c++) {
            int row = rowq, ch = chq + c;
            uint32_t d = (uint32_t)(row * APITCH + ch * 16);
            size_t g = hb + (size_t)(q0 + row) * HD_ + ch * 8;
            cp16(qhs + d, g_qh + g);
            cp16(qls + d, g_ql + g);
        }
        CP_COMMIT();
    }

    auto load_kv = [&](int t) {
        const int j0 = t * 64;
        const uint32_t stg = sb + QAREA + (uint32_t)(t & 1) * ASTAGE;
#pragma unroll
        for (int c = 0; c < 16; c++) {
            int idx = tid + 256 * c;
            int buf = idx >> 10, rem = idx & 1023;
            int row = rem >> 4, ch = rem & 15;
            const __nv_bfloat16* src = (buf == 0) ? g_kh : (buf == 1) ? g_kl
                                     : (buf == 2) ? g_vh : g_vl;
            cp16(stg + (uint32_t)(buf * KVBUF + row * APITCH + ch * 16),
                 src + hb + (size_t)(j0 + row) * HD_ + ch * 8);
        }
        CP_COMMIT();
    };

    load_kv(0);

    float o[16][4];
#pragma unroll
    for (int i = 0; i < 16; i++)
#pragma unroll
        for (int j = 0; j < 4; j++) o[i][j] = 0.f;
    float m0r = -1e30f, m1r = -1e30f, l0 = 0.f, l1 = 0.f;

    const int rg0 = q0 + 16 * wid + (lane >> 2);
    const int rg1 = rg0 + 8;
    const uint32_t qoff = (uint32_t)((16 * wid + (lane & 15)) * APITCH + ((lane >> 4) & 1) * 16);
    const uint32_t kbase = (uint32_t)((lane & 7) * APITCH + ((lane >> 4) & 1) * 8 * APITCH
                                      + ((lane >> 3) & 1) * 16);
    const uint32_t vbase = (uint32_t)((lane & 7) * APITCH + ((lane >> 3) & 1) * 8 * APITCH
                                      + ((lane >> 4) & 1) * 16);

    const int ntiles = q0 / 64 + 2;
    for (int t = 0; t < ntiles; t++) {
        if (t + 1 < ntiles) { load_kv(t + 1); CP_WAIT(1); }
        else                { CP_WAIT(0); }
        __syncthreads();

        const uint32_t stg = sb + QAREA + (uint32_t)(t & 1) * ASTAGE;
        const uint32_t khi_s = stg, klo_s = stg + KVBUF;
        const uint32_t vhi_s = stg + 2 * KVBUF, vlo_s = stg + 3 * KVBUF;
        const int j0 = t * 64;

        float sf[8][4];
#pragma unroll
        for (int i = 0; i < 8; i++)
#pragma unroll
            for (int j = 0; j < 4; j++) sf[i][j] = 0.f;

#pragma unroll
        for (int kf = 0; kf < 8; kf++) {
            uint32_t ah[4], al[4];
            ldsm_x4(ah, qhs + qoff + (uint32_t)(kf * 32));
            ldsm_x4(al, qls + qoff + (uint32_t)(kf * 32));
            uint32_t kb[8][2], kl2[8][2];
#pragma unroll
            for (int ntp = 0; ntp < 4; ntp++) {
                uint32_t r4[4];
                ldsm_x4(r4, khi_s + kbase + (uint32_t)(ntp * 16 * APITCH + kf * 32));
                kb[2 * ntp][0] = r4[0]; kb[2 * ntp][1] = r4[1];
                kb[2 * ntp + 1][0] = r4[2]; kb[2 * ntp + 1][1] = r4[3];
                ldsm_x4(r4, klo_s + kbase + (uint32_t)(ntp * 16 * APITCH + kf * 32));
                kl2[2 * ntp][0] = r4[0]; kl2[2 * ntp][1] = r4[1];
                kl2[2 * ntp + 1][0] = r4[2]; kl2[2 * ntp + 1][1] = r4[3];
            }
#pragma unroll
            for (int nt = 0; nt < 8; nt++) {
                mma_bf(sf[nt], ah, kb[nt]);
                mma_bf(sf[nt], ah, kl2[nt]);
                mma_bf(sf[nt], al, kb[nt]);
            }
        }

        if (t >= ntiles - 2) {
            const int cb = j0 + 2 * (lane & 3);
#pragma unroll
            for (int nt = 0; nt < 8; nt++) {
                int jg = cb + 8 * nt;
                if (jg > rg0)     sf[nt][0] = -1e30f;
                if (jg + 1 > rg0) sf[nt][1] = -1e30f;
                if (jg > rg1)     sf[nt][2] = -1e30f;
                if (jg + 1 > rg1) sf[nt][3] = -1e30f;
            }
        }

        float mt0 = -1e30f, mt1 = -1e30f;
#pragma unroll
        for (int nt = 0; nt < 8; nt++) {
            mt0 = fmaxf(mt0, fmaxf(sf[nt][0], sf[nt][1]));
            mt1 = fmaxf(mt1, fmaxf(sf[nt][2], sf[nt][3]));
        }
        mt0 = fmaxf(mt0, __shfl_xor_sync(0xffffffffu, mt0, 1));
        mt0 = fmaxf(mt0, __shfl_xor_sync(0xffffffffu, mt0, 2));
        mt1 = fmaxf(mt1, __shfl_xor_sync(0xffffffffu, mt1, 1));
        mt1 = fmaxf(mt1, __shfl_xor_sync(0xffffffffu, mt1, 2));
        float mn0 = fmaxf(m0r, mt0), mn1 = fmaxf(m1r, mt1);
        float c0 = ex2f(m0r - mn0), c1 = ex2f(m1r - mn1);
        m0r = mn0; m1r = mn1;
        float s0 = 0.f, s1 = 0.f;
#pragma unroll
        for (int nt = 0; nt < 8; nt++) {
            sf[nt][0] = ex2f(sf[nt][0] - mn0);
            sf[nt][1] = ex2f(sf[nt][1] - mn0);
            sf[nt][2] = ex2f(sf[nt][2] - mn1);
            sf[nt][3] = ex2f(sf[nt][3] - mn1);
            s0 += sf[nt][0] + sf[nt][1];
            s1 += sf[nt][2] + sf[nt][3];
        }
        s0 += __shfl_xor_sync(0xffffffffu, s0, 1);
        s0 += __shfl_xor_sync(0xffffffffu, s0, 2);
        s1 += __shfl_xor_sync(0xffffffffu, s1, 1);
        s1 += __shfl_xor_sync(0xffffffffu, s1, 2);
        l0 = l0 * c0 + s0;
        l1 = l1 * c1 + s1;
#pragma unroll
        for (int nt = 0; nt < 16; nt++) {
            o[nt][0] *= c0; o[nt][1] *= c0; o[nt][2] *= c1; o[nt][3] *= c1;
        }

#pragma unroll
        for (int kf = 0; kf < 4; kf++) {
            uint32_t ph[4], pl[4];
            split2(sf[2 * kf][0],     sf[2 * kf][1],     ph[0], pl[0]);
            split2(sf[2 * kf][2],     sf[2 * kf][3],     ph[1], pl[1]);
            split2(sf[2 * kf + 1][0], sf[2 * kf + 1][1], ph[2], pl[2]);
            split2(sf[2 * kf + 1][2], sf[2 * kf + 1][3], ph[3], pl[3]);
#pragma unroll
            for (int ntp = 0; ntp < 8; ntp++) {
                uint32_t vh4[4], vl4[4];
                const uint32_t va = vbase + (uint32_t)(kf * 16 * APITCH + ntp * 32);
                ldsm_x4t(vh4, vhi_s + va);
                ldsm_x4t(vl4, vlo_s + va);
                mma_bf(o[2 * ntp],     ph, vh4);
                mma_bf(o[2 * ntp],     ph, vl4);
                mma_bf(o[2 * ntp],     pl, vh4);
                mma_bf(o[2 * ntp + 1], ph, vh4 + 2);
                mma_bf(o[2 * ntp + 1], ph, vl4 + 2);
                mma_bf(o[2 * ntp + 1], pl, vh4 + 2);
            }
        }
        __syncthreads();
    }

    // epilogue: normalize + write fp16 A operand for out GEMM
    const float inv0 = 1.f / l0, inv1 = 1.f / l1;
    const int cb = h * HD_ + 2 * (lane & 3);
#pragma unroll
    for (int nt = 0; nt < 16; nt++) {
        const int col = cb + 8 * nt;
        __half2 p0 = __floats2half2_rn(o[nt][0] * inv0, o[nt][1] * inv0);
        __half2 p1 = __floats2half2_rn(o[nt][2] * inv1, o[nt][3] * inv1);
        *(__half2*)(g_ah + (size_t)(b * N_ + rg0) * D_ + col) = p0;
        *(__half2*)(g_ah + (size_t)(b * N_ + rg1) * D_ + col) = p1;
    }
}

// ---------------- launch ----------------
extern "C" void kernel_launch(void* const* d_in, const int* in_sizes, int n_in,
                              void* d_out, int out_size) {
    const float* x    = (const float*)d_in[0];
    const float* fq   = (const float*)d_in[1];
    const float* fk   = (const float*)d_in[2];
    const float* Wqkv = (const float*)d_in[5];
    const float* bqkv = (const float*)d_in[6];
    const float* Wout = (const float*)d_in[7];
    const float* bout = (const float*)d_in[8];

    float* out   = (float*)d_out;
    float* kvout = out + KVBASE;

    const int smem_gemm = 2 * STG;   // 61,440 B
    cudaFuncSetAttribute(gemm_mma<0, 3 * D_>, cudaFuncAttributeMaxDynamicSharedMemorySize, smem_gemm);
    cudaFuncSetAttribute(gemm_mma<1, D_>,     cudaFuncAttributeMaxDynamicSharedMemorySize, smem_gemm);
    cudaFuncSetAttribute(attn_mma, cudaFuncAttributeMaxDynamicSharedMemorySize, ASMEM);

    // 0) convert inputs
    conv_a<<<(M_ * D_ / 8) / 256, 256>>>(x);
    conv_w<0><<<dim3(3 * D_ / 32, D_ / 32), dim3(32, 8)>>>(Wqkv, 3 * D_);
    conv_w<1><<<dim3(D_ / 32, D_ / 32), dim3(32, 8)>>>(Wout, D_);

    // 1) QKV GEMM -> g_qkv (fp32)
    gemm_mma<0, 3 * D_><<<dim3(3 * D_ / 128, M_ / 128), 256, smem_gemm>>>(bqkv, nullptr);

    // 2) RoPE + bf16 hi/lo attention operands + fp32 KV cache
    rope_scatter<<<(B_ * H_ * N_ * 64) / 256, 256>>>(fq, fk, kvout);

    // 3) mma flash attention -> g_ah (fp16 A operand, normalized)
    attn_mma<<<dim3(N_ / 128, H_, B_), 256, ASMEM>>>();

    // 4) out GEMM -> d_out
    gemm_mma<1, D_><<<dim3(D_ / 128, M_ / 128), 256, smem_gemm>>>(bout, out);
}

// round 11
// speedup vs baseline: 4.8494x; 1.0701x over previous
#include <cuda_runtime.h>
#include <cuda_bf16.h>
#include <cuda_fp16.h>
#include <cstdint>

#define B_  2
#define N_  2048
#define D_  2048
#define H_  16
#define HD_ 128
#define M_  (B_*N_)              // 4096
#define KVBASE ((size_t)M_*D_)   // floats offset of next_prefix_kv in d_out
#define KVHALF ((size_t)B_*H_*N_*64)   // float2 elems in one (k or v) half

// ---------------- scratch (device globals; no allocation) ----------------
__device__ __half g_ah[(size_t)M_ * D_];                // A operand fp16 (x, then attn out)
__device__ __half g_wqkv_h[(size_t)3 * D_ * D_];        // [6144, 2048] K-major
__device__ __half g_wqkv_l[(size_t)3 * D_ * D_];
__device__ __half g_wout_h[(size_t)D_ * D_];            // [2048, 2048] K-major
__device__ __half g_wout_l[(size_t)D_ * D_];
// per-head bf16 operands for attention [b,h,n,128]
__device__ __nv_bfloat16 g_qh[(size_t)B_ * H_ * N_ * HD_];
__device__ __nv_bfloat16 g_ql[(size_t)B_ * H_ * N_ * HD_];
__device__ __nv_bfloat16 g_kh[(size_t)B_ * H_ * N_ * HD_];
__device__ __nv_bfloat16 g_kl[(size_t)B_ * H_ * N_ * HD_];
__device__ __nv_bfloat16 g_vh[(size_t)B_ * H_ * N_ * HD_];
__device__ __nv_bfloat16 g_vl[(size_t)B_ * H_ * N_ * HD_];

// ---------------- helpers ----------------
__device__ __forceinline__ uint32_t smem_u32(const void* p) {
    uint32_t a;
    asm("{ .reg .u64 t; cvta.to.shared.u64 t, %1; cvt.u32.u64 %0, t; }" : "=r"(a) : "l"(p));
    return a;
}
__device__ __forceinline__ void cp16(uint32_t dst, const void* src) {
    asm volatile("cp.async.cg.shared.global [%0], [%1], 16;" :: "r"(dst), "l"(src) : "memory");
}
#define CP_COMMIT()  asm volatile("cp.async.commit_group;" ::: "memory")
#define CP_WAIT(n)   asm volatile("cp.async.wait_group %0;" :: "n"(n) : "memory")

__device__ __forceinline__ void ldsm_x4(uint32_t* r, uint32_t a) {
    asm volatile("ldmatrix.sync.aligned.m8n8.x4.shared.b16 {%0,%1,%2,%3}, [%4];"
                 : "=r"(r[0]), "=r"(r[1]), "=r"(r[2]), "=r"(r[3]) : "r"(a));
}
__device__ __forceinline__ void ldsm_x4t(uint32_t* r, uint32_t a) {
    asm volatile("ldmatrix.sync.aligned.m8n8.x4.trans.shared.b16 {%0,%1,%2,%3}, [%4];"
                 : "=r"(r[0]), "=r"(r[1]), "=r"(r[2]), "=r"(r[3]) : "r"(a));
}
__device__ __forceinline__ void mma_bf(float* d, const uint32_t* a, const uint32_t* b) {
    asm volatile("mma.sync.aligned.m16n8k16.row.col.f32.bf16.bf16.f32 "
        "{%0,%1,%2,%3}, {%4,%5,%6,%7}, {%8,%9}, {%0,%1,%2,%3};"
        : "+f"(d[0]), "+f"(d[1]), "+f"(d[2]), "+f"(d[3])
        : "r"(a[0]), "r"(a[1]), "r"(a[2]), "r"(a[3]), "r"(b[0]), "r"(b[1]));
}
__device__ __forceinline__ void mma_fp(float* d, const uint32_t* a, const uint32_t* b) {
    asm volatile("mma.sync.aligned.m16n8k16.row.col.f32.f16.f16.f32 "
        "{%0,%1,%2,%3}, {%4,%5,%6,%7}, {%8,%9}, {%0,%1,%2,%3};"
        : "+f"(d[0]), "+f"(d[1]), "+f"(d[2]), "+f"(d[3])
        : "r"(a[0]), "r"(a[1]), "r"(a[2]), "r"(a[3]), "r"(b[0]), "r"(b[1]));
}
__device__ __forceinline__ float ex2f(float x) {
    float r; asm("ex2.approx.f32 %0, %1;" : "=f"(r) : "f"(x)); return r;
}
// pack two fp32 into bf16x2 with hi/lo residual split; low half = v0
__device__ __forceinline__ void split2(float v0, float v1, uint32_t& hi, uint32_t& lo) {
    uint32_t h;
    asm("cvt.rn.bf16x2.f32 %0, %1, %2;" : "=r"(h) : "f"(v1), "f"(v0));
    __nv_bfloat162 hb = *(__nv_bfloat162*)&h;
    float r0 = v0 - __bfloat162float(hb.x);
    float r1 = v1 - __bfloat162float(hb.y);
    uint32_t lw;
    asm("cvt.rn.bf16x2.f32 %0, %1, %2;" : "=r"(lw) : "f"(r1), "f"(r0));
    hi = h; lo = lw;
}
#define SCLQ (0.08838834764831845f * 1.4426950408889634f)   // log2e/sqrt(128)

// ---------------- x fp32 -> fp16 (A operand for QKV GEMM) ----------------
__global__ void conv_a(const float* __restrict__ src) {
    size_t i = (size_t)blockIdx.x * blockDim.x + threadIdx.x;   // per 8 floats
    const float4* s4 = (const float4*)src + i * 2;
    float4 a = s4[0], b = s4[1];
    float v[8] = {a.x, a.y, a.z, a.w, b.x, b.y, b.z, b.w};
    union { __half h[8]; uint4 u; } uh;
#pragma unroll
    for (int j = 0; j < 8; j++) uh.h[j] = __float2half_rn(v[j]);
    *(uint4*)(g_ah + i * 8) = uh.u;
}

// ---------------- W [K, N] fp32 -> fp16 hi/lo [N, K] (transpose) ----------------
template <int SEL>
__global__ void conv_w(const float* __restrict__ W, int N) {
    __half* hi = SEL ? g_wout_h : g_wqkv_h;
    __half* lo = SEL ? g_wout_l : g_wqkv_l;
    __shared__ float t[32][33];
    int n0 = blockIdx.x * 32, k0 = blockIdx.y * 32;
    int tx = threadIdx.x, ty = threadIdx.y;   // 32 x 8
#pragma unroll
    for (int i = 0; i < 4; i++)
        t[ty + 8 * i][tx] = W[(size_t)(k0 + ty + 8 * i) * N + n0 + tx];
    __syncthreads();
#pragma unroll
    for (int i = 0; i < 4; i++) {
        int n = n0 + ty + 8 * i, k = k0 + tx;
        float v = t[tx][ty + 8 * i];
        __half h = __float2half_rn(v);
        hi[(size_t)n * D_ + k] = h;
        lo[(size_t)n * D_ + k] = __float2half_rn(v - __half2float(h));
    }
}

// ---------------- fp16 mma GEMM (3-stage, fused RoPE epilogue for MODE 0) ----------
// MODE 0: A = g_ah (x), W = Wqkv hi/lo; epilogue = bias + RoPE + bf16 splits + KV cache
// MODE 1: A = g_ah (attn out), W = Wout hi/lo; epilogue = bias + fp32 store to Cparam
#define BKG 32
#define TPAD 80
#define TILE_B (128 * TPAD)     // 10240 per buffer
#define STG (3 * TILE_B)        // A, Wh, Wl -> 30720 per stage
#define NSTAGE 3
#define GSMEM (NSTAGE * STG)    // 92160
#define GT (D_ / BKG)           // 64

template <int MODE, int NN>
__global__ __launch_bounds__(256, 2)
void gemm_mma(const float* __restrict__ bias, float* __restrict__ Cparam,
              const float* __restrict__ fq, const float* __restrict__ fk,
              float* __restrict__ kvout) {
    extern __shared__ __align__(128) char sm[];
    const __half* Wh = (MODE == 0) ? g_wqkv_h : g_wout_h;
    const __half* Wl = (MODE == 0) ? g_wqkv_l : g_wout_l;
    const int m0 = blockIdx.y * 128, n0 = blockIdx.x * 128;
    const uint32_t sb = smem_u32(sm);
    const int tid = threadIdx.x, wid = tid >> 5, lane = tid & 31;
    const int wm = (wid >> 2) * 64;
    const int wn = (wid & 3) * 32;

    float d[4][4][4];
#pragma unroll
    for (int i = 0; i < 4; i++)
#pragma unroll
        for (int j = 0; j < 4; j++)
#pragma unroll
            for (int q = 0; q < 4; q++) d[i][j][q] = 0.f;

    // loader: 3 buffers x 512 chunks = 1536 chunks, 6 per thread
    auto load_tile = [&](int t) {
        const int k0 = t * BKG;
        const uint32_t st = sb + (uint32_t)(t % NSTAGE) * STG;
#pragma unroll
        for (int c = 0; c < 6; c++) {
            int idx = tid + 256 * c;           // 0..1535
            int buf = idx >> 9, rem = idx & 511;
            int row = rem >> 2, ch = rem & 3;
            const __half* sp = (buf == 0) ? (g_ah + (size_t)(m0 + row) * D_)
                             : (buf == 1) ? (Wh + (size_t)(n0 + row) * D_)
                                          : (Wl + (size_t)(n0 + row) * D_);
            cp16(st + (uint32_t)(buf * TILE_B + row * TPAD + ch * 16),
                 sp + k0 + ch * 8);
        }
        CP_COMMIT();
    };

    const int ar = lane & 15, ac = lane >> 4;
    const uint32_t aoff = (uint32_t)((wm + ar) * TPAD + ac * 16);
    // B x4 addressing (two 8-row frags per ldsm): rows wn+np*16+(lane&7)+8*((lane>>4)&1)
    const uint32_t boff = (uint32_t)((wn + (lane & 7) + 8 * ((lane >> 4) & 1)) * TPAD
                                     + ((lane >> 3) & 1) * 16);

    load_tile(0);
    load_tile(1);

    for (int t = 0; t < GT; t++) {
        if (t + 1 < GT) CP_WAIT(1); else CP_WAIT(0);
        __syncthreads();
        if (t + 2 < GT) load_tile(t + 2);

        const uint32_t st = sb + (uint32_t)(t % NSTAGE) * STG;
        uint32_t a[4][4], bh[4][2], bl[4][2];
#pragma unroll
        for (int ks = 0; ks < 2; ks++) {
            const uint32_t kbo = (uint32_t)(ks * 32);
#pragma unroll
            for (int mt = 0; mt < 4; mt++)
                ldsm_x4(a[mt], st + aoff + kbo + (uint32_t)(mt * 16 * TPAD));
#pragma unroll
            for (int np = 0; np < 2; np++) {
                uint32_t r4[4];
                ldsm_x4(r4, st + TILE_B + boff + kbo + (uint32_t)(np * 16 * TPAD));
                bh[2 * np][0] = r4[0]; bh[2 * np][1] = r4[1];
                bh[2 * np + 1][0] = r4[2]; bh[2 * np + 1][1] = r4[3];
                ldsm_x4(r4, st + 2 * TILE_B + boff + kbo + (uint32_t)(np * 16 * TPAD));
                bl[2 * np][0] = r4[0]; bl[2 * np][1] = r4[1];
                bl[2 * np + 1][0] = r4[2]; bl[2 * np + 1][1] = r4[3];
            }
#pragma unroll
            for (int mt = 0; mt < 4; mt++)
#pragma unroll
                for (int nt = 0; nt < 4; nt++) mma_fp(d[mt][nt], a[mt], bh[nt]);
#pragma unroll
            for (int mt = 0; mt < 4; mt++)
#pragma unroll
                for (int nt = 0; nt < 4; nt++) mma_fp(d[mt][nt], a[mt], bl[nt]);
        }
    }

    const int erow = lane >> 2, ecol = (lane & 3) * 2;

    if (MODE == 1) {
#pragma unroll
        for (int mt = 0; mt < 4; mt++) {
#pragma unroll
            for (int nt = 0; nt < 4; nt++) {
                const int col = n0 + wn + nt * 8 + ecol;
                const float2 bv = *(const float2*)(bias + col);
                const int row = m0 + wm + mt * 16 + erow;
                float2 v0 = make_float2(d[mt][nt][0] + bv.x, d[mt][nt][1] + bv.y);
                float2 v1 = make_float2(d[mt][nt][2] + bv.x, d[mt][nt][3] + bv.y);
                *(float2*)(Cparam + (size_t)row * NN + col)       = v0;
                *(float2*)(Cparam + (size_t)(row + 8) * NN + col) = v1;
            }
        }
    } else {
        // fused RoPE epilogue: this CTA's 128 cols lie in one segment & one head
        const int seg = n0 >> 11;              // 0=q, 1=k, 2=v
        const int hh = (n0 & 2047) >> 7;
#pragma unroll
        for (int mt = 0; mt < 4; mt++) {
            const int row = m0 + wm + mt * 16 + erow;
            const int bb = row >> 11;
            const int nn0 = row & 2047, nn1 = nn0 + 8;
#pragma unroll
            for (int nt = 0; nt < 4; nt++) {
                const int col = n0 + wn + nt * 8 + ecol;
                const int p = ((wn + nt * 8 + ecol) & 127) >> 1;  // pair index in head
                const float2 bv = *(const float2*)(bias + col);
                float e0 = d[mt][nt][0] + bv.x, e1 = d[mt][nt][1] + bv.y;
                float e2 = d[mt][nt][2] + bv.x, e3 = d[mt][nt][3] + bv.y;
                const size_t i0 = ((size_t)(bb * H_ + hh) * N_ + nn0) * 64 + p;
                const size_t i1 = i0 + 8 * 64;
                uint32_t hi, lo;
                if (seg == 0) {
                    float s, c;
                    sincosf(fq[nn0 * 64 + p], &s, &c);
                    split2((e0 * c - e1 * s) * SCLQ, (e0 * s + e1 * c) * SCLQ, hi, lo);
                    ((uint32_t*)g_qh)[i0] = hi; ((uint32_t*)g_ql)[i0] = lo;
                    sincosf(fq[nn1 * 64 + p], &s, &c);
                    split2((e2 * c - e3 * s) * SCLQ, (e2 * s + e3 * c) * SCLQ, hi, lo);
                    ((uint32_t*)g_qh)[i1] = hi; ((uint32_t*)g_ql)[i1] = lo;
                } else if (seg == 1) {
                    ((float2*)kvout)[i0] = make_float2(e0, e1);   // pre-RoPE k
                    ((float2*)kvout)[i1] = make_float2(e2, e3);
                    float s, c;
                    sincosf(fk[nn0 * 64 + p], &s, &c);
                    split2(e0 * c - e1 * s, e0 * s + e1 * c, hi, lo);
                    ((uint32_t*)g_kh)[i0] = hi; ((uint32_t*)g_kl)[i0] = lo;
                    sincosf(fk[nn1 * 64 + p], &s, &c);
                    split2(e2 * c - e3 * s, e2 * s + e3 * c, hi, lo);
                    ((uint32_t*)g_kh)[i1] = hi; ((uint32_t*)g_kl)[i1] = lo;
                } else {
                    ((float2*)kvout)[i0 + KVHALF] = make_float2(e0, e1);
                    ((float2*)kvout)[i1 + KVHALF] = make_float2(e2, e3);
                    split2(e0, e1, hi, lo);
                    ((uint32_t*)g_vh)[i0] = hi; ((uint32_t*)g_vl)[i0] = lo;
                    split2(e2, e3, hi, lo);
                    ((uint32_t*)g_vh)[i1] = hi; ((uint32_t*)g_vl)[i1] = lo;
                }
            }
        }
    }
}

// ---------------- mma flash attention (bf16 3-split, causal) ----------------
#define APITCH 272
#define QAREA  (2 * 128 * APITCH)
#define KVBUF  (64 * APITCH)
#define ASTAGE (4 * KVBUF)
#define ASMEM  (QAREA + 2 * ASTAGE)   // 208896

__global__ __launch_bounds__(256, 1)
void attn_mma() {
    extern __shared__ __align__(128) char sm[];
    const int tid = threadIdx.x, wid = tid >> 5, lane = tid & 31;
    const int h = blockIdx.y, b = blockIdx.z;
    const int q0 = (gridDim.x - 1 - blockIdx.x) * 128;
    const int bh = b * H_ + h;
    const size_t hb = (size_t)bh * N_ * HD_;

    const uint32_t sb = smem_u32(sm);
    const uint32_t qhs = sb, qls = sb + (uint32_t)(128 * APITCH);

    {
        const int rowq = tid >> 1, chq = (tid & 1) * 8;
#pragma unroll
        for (int c = 0; c < 8; c++) {
            int row = rowq, ch = chq + c;
            uint32_t d = (uint32_t)(row * APITCH + ch * 16);
            size_t g = hb + (size_t)(q0 + row) * HD_ + ch * 8;
            cp16(qhs + d, g_qh + g);
            cp16(qls + d, g_ql + g);
        }
        CP_COMMIT();
    }

    auto load_kv = [&](int t) {
        const int j0 = t * 64;
        const uint32_t stg = sb + QAREA + (uint32_t)(t & 1) * ASTAGE;
#pragma unroll
        for (int c = 0; c < 16; c++) {
            int idx = tid + 256 * c;
            int buf = idx >> 10, rem = idx & 1023;
            int row = rem >> 4, ch = rem & 15;
            const __nv_bfloat16* src = (buf == 0) ? g_kh : (buf == 1) ? g_kl
                                     : (buf == 2) ? g_vh : g_vl;
            cp16(stg + (uint32_t)(buf * KVBUF + row * APITCH + ch * 16),
                 src + hb + (size_t)(j0 + row) * HD_ + ch * 8);
        }
        CP_COMMIT();
    };

    load_kv(0);

    float o[16][4];
#pragma unroll
    for (int i = 0; i < 16; i++)
#pragma unroll
        for (int j = 0; j < 4; j++) o[i][j] = 0.f;
    float m0r = -1e30f, m1r = -1e30f, l0 = 0.f, l1 = 0.f;

    const int rg0 = q0 + 16 * wid + (lane >> 2);
    const int rg1 = rg0 + 8;
    const uint32_t qoff = (uint32_t)((16 * wid + (lane & 15)) * APITCH + ((lane >> 4) & 1) * 16);
    const uint32_t kbase = (uint32_t)((lane & 7) * APITCH + ((lane >> 4) & 1) * 8 * APITCH
                                      + ((lane >> 3) & 1) * 16);
    const uint32_t vbase = (uint32_t)((lane & 7) * APITCH + ((lane >> 3) & 1) * 8 * APITCH
                                      + ((lane >> 4) & 1) * 16);

    const int ntiles = q0 / 64 + 2;
    for (int t = 0; t < ntiles; t++) {
        if (t + 1 < ntiles) { load_kv(t + 1); CP_WAIT(1); }
        else                { CP_WAIT(0); }
        __syncthreads();

        const uint32_t stg = sb + QAREA + (uint32_t)(t & 1) * ASTAGE;
        const uint32_t khi_s = stg, klo_s = stg + KVBUF;
        const uint32_t vhi_s = stg + 2 * KVBUF, vlo_s = stg + 3 * KVBUF;
        const int j0 = t * 64;

        float sf[8][4];
#pragma unroll
        for (int i = 0; i < 8; i++)
#pragma unroll
            for (int j = 0; j < 4; j++) sf[i][j] = 0.f;

#pragma unroll
        for (int kf = 0; kf < 8; kf++) {
            uint32_t ah[4], al[4];
            ldsm_x4(ah, qhs + qoff + (uint32_t)(kf * 32));
            ldsm_x4(al, qls + qoff + (uint32_t)(kf * 32));
            uint32_t kb[8][2], kl2[8][2];
#pragma unroll
            for (int ntp = 0; ntp < 4; ntp++) {
                uint32_t r4[4];
                ldsm_x4(r4, khi_s + kbase + (uint32_t)(ntp * 16 * APITCH + kf * 32));
                kb[2 * ntp][0] = r4[0]; kb[2 * ntp][1] = r4[1];
                kb[2 * ntp + 1][0] = r4[2]; kb[2 * ntp + 1][1] = r4[3];
                ldsm_x4(r4, klo_s + kbase + (uint32_t)(ntp * 16 * APITCH + kf * 32));
                kl2[2 * ntp][0] = r4[0]; kl2[2 * ntp][1] = r4[1];
                kl2[2 * ntp + 1][0] = r4[2]; kl2[2 * ntp + 1][1] = r4[3];
            }
#pragma unroll
            for (int nt = 0; nt < 8; nt++) {
                mma_bf(sf[nt], ah, kb[nt]);
                mma_bf(sf[nt], ah, kl2[nt]);
                mma_bf(sf[nt], al, kb[nt]);
            }
        }

        if (t >= ntiles - 2) {
            const int cb = j0 + 2 * (lane & 3);
#pragma unroll
            for (int nt = 0; nt < 8; nt++) {
                int jg = cb + 8 * nt;
                if (jg > rg0)     sf[nt][0] = -1e30f;
                if (jg + 1 > rg0) sf[nt][1] = -1e30f;
                if (jg > rg1)     sf[nt][2] = -1e30f;
                if (jg + 1 > rg1) sf[nt][3] = -1e30f;
            }
        }

        float mt0 = -1e30f, mt1 = -1e30f;
#pragma unroll
        for (int nt = 0; nt < 8; nt++) {
            mt0 = fmaxf(mt0, fmaxf(sf[nt][0], sf[nt][1]));
            mt1 = fmaxf(mt1, fmaxf(sf[nt][2], sf[nt][3]));
        }
        mt0 = fmaxf(mt0, __shfl_xor_sync(0xffffffffu, mt0, 1));
        mt0 = fmaxf(mt0, __shfl_xor_sync(0xffffffffu, mt0, 2));
        mt1 = fmaxf(mt1, __shfl_xor_sync(0xffffffffu, mt1, 1));
        mt1 = fmaxf(mt1, __shfl_xor_sync(0xffffffffu, mt1, 2));
        float mn0 = fmaxf(m0r, mt0), mn1 = fmaxf(m1r, mt1);
        float c0 = ex2f(m0r - mn0), c1 = ex2f(m1r - mn1);
        m0r = mn0; m1r = mn1;
        float s0 = 0.f, s1 = 0.f;
#pragma unroll
        for (int nt = 0; nt < 8; nt++) {
            sf[nt][0] = ex2f(sf[nt][0] - mn0);
            sf[nt][1] = ex2f(sf[nt][1] - mn0);
            sf[nt][2] = ex2f(sf[nt][2] - mn1);
            sf[nt][3] = ex2f(sf[nt][3] - mn1);
            s0 += sf[nt][0] + sf[nt][1];
            s1 += sf[nt][2] + sf[nt][3];
        }
        s0 += __shfl_xor_sync(0xffffffffu, s0, 1);
        s0 += __shfl_xor_sync(0xffffffffu, s0, 2);
        s1 += __shfl_xor_sync(0xffffffffu, s1, 1);
        s1 += __shfl_xor_sync(0xffffffffu, s1, 2);
        l0 = l0 * c0 + s0;
        l1 = l1 * c1 + s1;
#pragma unroll
        for (int nt = 0; nt < 16; nt++) {
            o[nt][0] *= c0; o[nt][1] *= c0; o[nt][2] *= c1; o[nt][3] *= c1;
        }

#pragma unroll
        for (int kf = 0; kf < 4; kf++) {
            uint32_t ph[4], pl[4];
            split2(sf[2 * kf][0],     sf[2 * kf][1],     ph[0], pl[0]);
            split2(sf[2 * kf][2],     sf[2 * kf][3],     ph[1], pl[1]);
            split2(sf[2 * kf + 1][0], sf[2 * kf + 1][1], ph[2], pl[2]);
            split2(sf[2 * kf + 1][2], sf[2 * kf + 1][3], ph[3], pl[3]);
#pragma unroll
            for (int ntp = 0; ntp < 8; ntp++) {
                uint32_t vh4[4], vl4[4];
                const uint32_t va = vbase + (uint32_t)(kf * 16 * APITCH + ntp * 32);
                ldsm_x4t(vh4, vhi_s + va);
                ldsm_x4t(vl4, vlo_s + va);
                mma_bf(o[2 * ntp],     ph, vh4);
                mma_bf(o[2 * ntp],     ph, vl4);
                mma_bf(o[2 * ntp],     pl, vh4);
                mma_bf(o[2 * ntp + 1], ph, vh4 + 2);
                mma_bf(o[2 * ntp + 1], ph, vl4 + 2);
                mma_bf(o[2 * ntp + 1], pl, vh4 + 2);
            }
        }
        __syncthreads();
    }

    // epilogue: normalize + write fp16 A operand for out GEMM
    const float inv0 = 1.f / l0, inv1 = 1.f / l1;
    const int cb = h * HD_ + 2 * (lane & 3);
#pragma unroll
    for (int nt = 0; nt < 16; nt++) {
        const int col = cb + 8 * nt;
        __half2 p0 = __floats2half2_rn(o[nt][0] * inv0, o[nt][1] * inv0);
        __half2 p1 = __floats2half2_rn(o[nt][2] * inv1, o[nt][3] * inv1);
        *(__half2*)(g_ah + (size_t)(b * N_ + rg0) * D_ + col) = p0;
        *(__half2*)(g_ah + (size_t)(b * N_ + rg1) * D_ + col) = p1;
    }
}

// ---------------- launch ----------------
extern "C" void kernel_launch(void* const* d_in, const int* in_sizes, int n_in,
                              void* d_out, int out_size) {
    const float* x    = (const float*)d_in[0];
    const float* fq   = (const float*)d_in[1];
    const float* fk   = (const float*)d_in[2];
    const float* Wqkv = (const float*)d_in[5];
    const float* bqkv = (const float*)d_in[6];
    const float* Wout = (const float*)d_in[7];
    const float* bout = (const float*)d_in[8];

    float* out   = (float*)d_out;
    float* kvout = out + KVBASE;

    cudaFuncSetAttribute(gemm_mma<0, 3 * D_>, cudaFuncAttributeMaxDynamicSharedMemorySize, GSMEM);
    cudaFuncSetAttribute(gemm_mma<1, D_>,     cudaFuncAttributeMaxDynamicSharedMemorySize, GSMEM);
    cudaFuncSetAttribute(attn_mma, cudaFuncAttributeMaxDynamicSharedMemorySize, ASMEM);

    // 0) convert inputs
    conv_a<<<(M_ * D_ / 8) / 256, 256>>>(x);
    conv_w<0><<<dim3(3 * D_ / 32, D_ / 32), dim3(32, 8)>>>(Wqkv, 3 * D_);
    conv_w<1><<<dim3(D_ / 32, D_ / 32), dim3(32, 8)>>>(Wout, D_);

    // 1) QKV GEMM + fused bias/RoPE/splits/KV-cache
    gemm_mma<0, 3 * D_><<<dim3(3 * D_ / 128, M_ / 128), 256, GSMEM>>>(bqkv, nullptr, fq, fk, kvout);

    // 2) mma flash attention -> g_ah (fp16 A operand, normalized)
    attn_mma<<<dim3(N_ / 128, H_, B_), 256, ASMEM>>>();

    // 3) out GEMM -> d_out
    gemm_mma<1, D_><<<dim3(D_ / 128, M_ / 128), 256, GSMEM>>>(bout, out, nullptr, nullptr, nullptr);
}